// round 1
// baseline (speedup 1.0000x reference)
#include <cuda_runtime.h>
#include <math.h>

#define BB 512
#define SS 1024
#define DIN 64
#define HH 64
#define SDIM 4

// Scratch (static device globals — allocation-guard-safe)
__device__ float g_pre[BB * SS * HH];   // 134 MB: h @ Wc1[:,4:]^T + bc1
__device__ float g_bx[BB * SS * SDIM];  // 8 MB:  h @ Wi^T + bi

// ---------- f32x2 helpers (Blackwell FFMA2 path) ----------
__device__ __forceinline__ unsigned long long pk2(float lo, float hi) {
    unsigned long long r;
    asm("mov.b64 %0, {%1,%2};" : "=l"(r) : "f"(lo), "f"(hi));
    return r;
}
__device__ __forceinline__ unsigned long long dup2(float x) {
    unsigned long long r;
    asm("mov.b64 %0, {%1,%1};" : "=l"(r) : "f"(x));
    return r;
}
__device__ __forceinline__ unsigned long long fma2(unsigned long long a,
                                                   unsigned long long b,
                                                   unsigned long long c) {
    unsigned long long d;
    asm("fma.rn.f32x2 %0, %1, %2, %3;" : "=l"(d) : "l"(a), "l"(b), "l"(c));
    return d;
}
__device__ __forceinline__ float lo2(unsigned long long v) { return __uint_as_float((unsigned)v); }
__device__ __forceinline__ float hi2(unsigned long long v) { return __uint_as_float((unsigned)(v >> 32)); }

__device__ __forceinline__ float tanh_fast(float x) {
    float y;
    asm("tanh.approx.f32 %0, %1;" : "=f"(y) : "f"(x));
    return y;
}
__device__ __forceinline__ float sigm(float x) { return 1.f / (1.f + expf(-x)); }

// ============================================================================
// Kernel A: per-token parallel precompute.
// Block = 128 threads (4 warps), 32 tokens/block. lane = token, warp = 16 cols.
// GEMM1: h = x@W1^T + b1 -> LN -> exact GELU (erff)
// GEMM2: pre = h@Wc1[:,4:]^T + bc1 ; bx = h@Wi^T + bi
// ============================================================================
__global__ __launch_bounds__(128, 4) void prep_kernel(
    const float* __restrict__ x, const float* __restrict__ W1, const float* __restrict__ b1,
    const float* __restrict__ ln_g, const float* __restrict__ ln_b,
    const float* __restrict__ Wi, const float* __restrict__ bi,
    const float* __restrict__ Wc1, const float* __restrict__ bc1)
{
    __shared__ __align__(16) float sW1[64 * 64];   // [k*64+j] = W1[j][k]; reused as hs[h*33+t]
    __shared__ __align__(16) float sWc1[64 * 64];  // [h*64+j] = Wc1[j][4+h]
    __shared__ __align__(16) float sWi[64 * 4];    // [h*4+i]  = Wi[i][h]
    __shared__ __align__(16) float sx[64 * 33];    // xs [k*33+t]; reused as ps [j*33+t]
    __shared__ float2 sred[4][32];

    const int tid  = threadIdx.x;
    const int lane = tid & 31;
    const int wid  = tid >> 5;
    const int tokbase = blockIdx.x * 32;

    // Load weights (transposed; L1 absorbs intra-block sector reuse)
#pragma unroll
    for (int it = 0; it < 32; it++) {
        int idx = it * 128 + tid;          // 4096
        int k = idx >> 6, j = idx & 63;
        sW1[idx]  = W1[j * 64 + k];
        sWc1[idx] = Wc1[j * 68 + 4 + k];
    }
#pragma unroll
    for (int it = 0; it < 2; it++) {
        int idx = it * 128 + tid;          // 256
        int h = idx >> 2, i = idx & 3;
        sWi[idx] = Wi[i * 64 + h];
    }
    // Stage x transposed: xs[k][t]
#pragma unroll
    for (int it = 0; it < 16; it++) {
        int idx = it * 128 + tid;          // 2048
        int t = idx >> 6, k = idx & 63;
        sx[k * 33 + t] = x[(tokbase + t) * 64 + k];
    }
    __syncthreads();

    const int jb = wid * 16;

    // ---- GEMM1 (acc initialized with b1) ----
    unsigned long long acc[8];
#pragma unroll
    for (int p = 0; p < 8; p++)
        acc[p] = pk2(__ldg(b1 + jb + 2 * p), __ldg(b1 + jb + 2 * p + 1));

#pragma unroll 8
    for (int k = 0; k < 64; k++) {
        float xk = sx[k * 33 + lane];
        unsigned long long xk2 = dup2(xk);
        const ulonglong2* wp = reinterpret_cast<const ulonglong2*>(&sW1[k * 64 + jb]);
        ulonglong2 w0 = wp[0], w1 = wp[1], w2 = wp[2], w3 = wp[3];
        acc[0] = fma2(w0.x, xk2, acc[0]);
        acc[1] = fma2(w0.y, xk2, acc[1]);
        acc[2] = fma2(w1.x, xk2, acc[2]);
        acc[3] = fma2(w1.y, xk2, acc[3]);
        acc[4] = fma2(w2.x, xk2, acc[4]);
        acc[5] = fma2(w2.y, xk2, acc[5]);
        acc[6] = fma2(w3.x, xk2, acc[6]);
        acc[7] = fma2(w3.y, xk2, acc[7]);
    }

    // ---- LayerNorm across 64 cols (cross-warp) ----
    float hv[16];
#pragma unroll
    for (int p = 0; p < 8; p++) { hv[2 * p] = lo2(acc[p]); hv[2 * p + 1] = hi2(acc[p]); }
    float s1v = 0.f, s2v = 0.f;
#pragma unroll
    for (int q = 0; q < 16; q++) { s1v += hv[q]; s2v = fmaf(hv[q], hv[q], s2v); }
    sred[wid][lane] = make_float2(s1v, s2v);
    __syncthreads();   // all GEMM1 reads of sW1 complete beyond this point

    float su = 0.f, sq = 0.f;
#pragma unroll
    for (int w = 0; w < 4; w++) { float2 r = sred[w][lane]; su += r.x; sq += r.y; }
    float mu   = su * (1.f / 64.f);
    float var  = fmaf(sq, 1.f / 64.f, -mu * mu);
    float rstd = rsqrtf(var + 1e-5f);

    // ---- normalize + exact GELU, stage hs into the sW1 region ----
#pragma unroll
    for (int q = 0; q < 16; q++) {
        int j = jb + q;
        float v  = fmaf((hv[q] - mu) * rstd, __ldg(ln_g + j), __ldg(ln_b + j));
        float ge = 0.5f * v * (1.f + erff(v * 0.70710678118654752f));
        sW1[j * 33 + lane] = ge;
    }
    __syncthreads();

    // ---- GEMM2: pre (acc initialized with bc1) ----
    unsigned long long pa[8];
#pragma unroll
    for (int p = 0; p < 8; p++)
        pa[p] = pk2(__ldg(bc1 + jb + 2 * p), __ldg(bc1 + jb + 2 * p + 1));

#pragma unroll 8
    for (int h = 0; h < 64; h++) {
        float hvv = sW1[h * 33 + lane];
        unsigned long long h2 = dup2(hvv);
        const ulonglong2* wp = reinterpret_cast<const ulonglong2*>(&sWc1[h * 64 + jb]);
        ulonglong2 w0 = wp[0], w1 = wp[1], w2 = wp[2], w3 = wp[3];
        pa[0] = fma2(w0.x, h2, pa[0]);
        pa[1] = fma2(w0.y, h2, pa[1]);
        pa[2] = fma2(w1.x, h2, pa[2]);
        pa[3] = fma2(w1.y, h2, pa[3]);
        pa[4] = fma2(w2.x, h2, pa[4]);
        pa[5] = fma2(w2.y, h2, pa[5]);
        pa[6] = fma2(w3.x, h2, pa[6]);
        pa[7] = fma2(w3.y, h2, pa[7]);
    }
    // stage pre transposed into sx (x no longer needed)
#pragma unroll
    for (int p = 0; p < 8; p++) {
        int j = jb + 2 * p;
        sx[j * 33 + lane]       = lo2(pa[p]);
        sx[(j + 1) * 33 + lane] = hi2(pa[p]);
    }

    // ---- bx = h@Wi^T + bi (warp 0 only) ----
    if (wid == 0) {
        unsigned long long bxa0 = pk2(__ldg(bi + 0), __ldg(bi + 1));
        unsigned long long bxa1 = pk2(__ldg(bi + 2), __ldg(bi + 3));
#pragma unroll 8
        for (int h = 0; h < 64; h++) {
            float hvv = sW1[h * 33 + lane];
            unsigned long long h2 = dup2(hvv);
            const ulonglong2 wiv = *reinterpret_cast<const ulonglong2*>(&sWi[h * 4]);
            bxa0 = fma2(wiv.x, h2, bxa0);
            bxa1 = fma2(wiv.y, h2, bxa1);
        }
        float4 bo = make_float4(lo2(bxa0), hi2(bxa0), lo2(bxa1), hi2(bxa1));
        *reinterpret_cast<float4*>(&g_bx[(tokbase + lane) * 4]) = bo;
    }
    __syncthreads();

    // ---- coalesced writeout of pre ----
    float* preg = g_pre + (size_t)tokbase * 64;
#pragma unroll
    for (int it = 0; it < 16; it++) {
        int idx = it * 128 + tid;
        int t = idx >> 6, j = idx & 63;
        preg[idx] = sx[j * 33 + t];
    }
}

// ============================================================================
// Kernel B: sequential scan. One warp per batch element; lane owns cols 2l,2l+1.
// Per step: s_lin = a*s + bx; u = pre + s_lin@Wc1s; g = gelu(u) (tanh-approx,
// error enters only via x0.01 correction); c = g@Wc2^T + bc2 (butterfly);
// s = s_lin + corr_scale*tanh(c). Depth-2 prefetch of pre/bx.
// ============================================================================
__global__ __launch_bounds__(32) void scan_kernel(
    const float* __restrict__ Wc1, const float* __restrict__ Wc2, const float* __restrict__ bc2,
    const float* __restrict__ corr_scale,
    const float* __restrict__ A_level, const float* __restrict__ A_trend,
    const float* __restrict__ A_gamma, const float* __restrict__ A_resid,
    const float* __restrict__ omega,
    float* __restrict__ out)
{
    const int b    = blockIdx.x;
    const int lane = threadIdx.x;
    const int j0   = lane * 2;

    float wS0[4], wS1[4], w20[4], w21[4], bc[4];
#pragma unroll
    for (int i = 0; i < 4; i++) {
        wS0[i] = __ldg(Wc1 + j0 * 68 + i);
        wS1[i] = __ldg(Wc1 + (j0 + 1) * 68 + i);
        w20[i] = __ldg(Wc2 + i * 64 + j0);
        w21[i] = __ldg(Wc2 + i * 64 + j0 + 1);
        bc[i]  = __ldg(bc2 + i);
    }
    const float cs = __ldg(corr_scale);
    const float a0 = sigm(__ldg(A_level)) * 0.15f + 0.85f;
    const float a1 = sigm(__ldg(A_trend)) * 0.25f + 0.7f;
    const float a2 = (sigm(__ldg(A_gamma)) * 0.2f + 0.8f) * cosf(__ldg(omega));
    const float a3 = sigm(__ldg(A_resid)) * 0.4f;

    const float* prep = g_pre + ((size_t)b * SS) * 64 + j0;
    const float* bxp  = g_bx  + ((size_t)b * SS) * 4;
    float* outp       = out   + ((size_t)b * SS) * 4;

    float s0 = 0.f, s1 = 0.f, s2 = 0.f, s3 = 0.f;

    float2 prb[2];
    float4 bxb[2];
    prb[0] = *reinterpret_cast<const float2*>(prep);
    bxb[0] = *reinterpret_cast<const float4*>(bxp);
    prb[1] = *reinterpret_cast<const float2*>(prep + 64);
    bxb[1] = *reinterpret_cast<const float4*>(bxp + 4);

#pragma unroll 2
    for (int t = 0; t < SS; t++) {
        int tp = t + 2;
        if (tp >= SS) tp = SS - 1;
        float2 prn = *reinterpret_cast<const float2*>(prep + (size_t)tp * 64);
        float4 bxn = *reinterpret_cast<const float4*>(bxp + (size_t)tp * 4);
        float2 pr = prb[t & 1];
        float4 bx = bxb[t & 1];

        float sl0 = fmaf(a0, s0, bx.x);
        float sl1 = fmaf(a1, s1, bx.y);
        float sl2 = fmaf(a2, s2, bx.z);
        float sl3 = fmaf(a3, s3, bx.w);

        float u0 = fmaf(sl0, wS0[0], fmaf(sl1, wS0[1], fmaf(sl2, wS0[2], fmaf(sl3, wS0[3], pr.x))));
        float u1 = fmaf(sl0, wS1[0], fmaf(sl1, wS1[1], fmaf(sl2, wS1[2], fmaf(sl3, wS1[3], pr.y))));

        // fast GELU (tanh form); error only enters via x0.01 correction path
        float q0 = u0 * u0;
        float in0 = u0 * fmaf(0.0356774081f, q0, 0.7978845608f);
        float g0 = 0.5f * u0 * (1.f + tanh_fast(in0));
        float q1 = u1 * u1;
        float in1 = u1 * fmaf(0.0356774081f, q1, 0.7978845608f);
        float g1 = 0.5f * u1 * (1.f + tanh_fast(in1));

        float p0 = fmaf(g0, w20[0], g1 * w21[0]);
        float p1 = fmaf(g0, w20[1], g1 * w21[1]);
        float p2 = fmaf(g0, w20[2], g1 * w21[2]);
        float p3 = fmaf(g0, w20[3], g1 * w21[3]);
#pragma unroll
        for (int off = 16; off; off >>= 1) {
            p0 += __shfl_xor_sync(0xffffffffu, p0, off);
            p1 += __shfl_xor_sync(0xffffffffu, p1, off);
            p2 += __shfl_xor_sync(0xffffffffu, p2, off);
            p3 += __shfl_xor_sync(0xffffffffu, p3, off);
        }
        float th0 = tanh_fast(p0 + bc[0]);
        float th1 = tanh_fast(p1 + bc[1]);
        float th2 = tanh_fast(p2 + bc[2]);
        float th3 = tanh_fast(p3 + bc[3]);
        s0 = fmaf(cs, th0, sl0);
        s1 = fmaf(cs, th1, sl1);
        s2 = fmaf(cs, th2, sl2);
        s3 = fmaf(cs, th3, sl3);

        if (lane == 0) {
            *reinterpret_cast<float4*>(outp + (size_t)t * 4) = make_float4(s0, s1, s2, s3);
        }
        prb[t & 1] = prn;
        bxb[t & 1] = bxn;
    }
}

extern "C" void kernel_launch(void* const* d_in, const int* in_sizes, int n_in,
                              void* d_out, int out_size)
{
    const float* x          = (const float*)d_in[0];
    const float* W1         = (const float*)d_in[1];
    const float* b1         = (const float*)d_in[2];
    const float* ln_g       = (const float*)d_in[3];
    const float* ln_b       = (const float*)d_in[4];
    const float* Wi         = (const float*)d_in[5];
    const float* bi         = (const float*)d_in[6];
    const float* Wc1        = (const float*)d_in[7];
    const float* bc1        = (const float*)d_in[8];
    const float* Wc2        = (const float*)d_in[9];
    const float* bc2        = (const float*)d_in[10];
    const float* corr_scale = (const float*)d_in[11];
    const float* A_level    = (const float*)d_in[12];
    const float* A_trend    = (const float*)d_in[13];
    const float* A_gamma    = (const float*)d_in[14];
    const float* A_resid    = (const float*)d_in[15];
    const float* omega      = (const float*)d_in[16];
    float* out = (float*)d_out;

    prep_kernel<<<(BB * SS) / 32, 128>>>(x, W1, b1, ln_g, ln_b, Wi, bi, Wc1, bc1);
    scan_kernel<<<BB, 32>>>(Wc1, Wc2, bc2, corr_scale,
                            A_level, A_trend, A_gamma, A_resid, omega, out);
}

// round 2
// speedup vs baseline: 1.6688x; 1.6688x over previous
#include <cuda_runtime.h>
#include <math.h>

#define BB 512
#define SS 1024
#define DIN 64
#define HH 64
#define SDIM 4
#define NTILES ((BB * SS) / 32)   // 16384 tiles of 32 tokens
#define PREP_GRID 592             // 148 SMs * 4 blocks

// Scratch (static device globals — allocation-guard-safe)
__device__ float g_pre[BB * SS * HH];   // 134 MB: h @ Wc1[:,4:]^T + bc1
__device__ float g_bx[BB * SS * SDIM];  // 8 MB:  h @ Wi^T + bi

// ---------- f32x2 helpers (Blackwell FFMA2 path) ----------
__device__ __forceinline__ unsigned long long pk2(float lo, float hi) {
    unsigned long long r;
    asm("mov.b64 %0, {%1,%2};" : "=l"(r) : "f"(lo), "f"(hi));
    return r;
}
__device__ __forceinline__ unsigned long long dup2(float x) {
    unsigned long long r;
    asm("mov.b64 %0, {%1,%1};" : "=l"(r) : "f"(x));
    return r;
}
__device__ __forceinline__ unsigned long long fma2(unsigned long long a,
                                                   unsigned long long b,
                                                   unsigned long long c) {
    unsigned long long d;
    asm("fma.rn.f32x2 %0, %1, %2, %3;" : "=l"(d) : "l"(a), "l"(b), "l"(c));
    return d;
}
__device__ __forceinline__ float lo2(unsigned long long v) { return __uint_as_float((unsigned)v); }
__device__ __forceinline__ float hi2(unsigned long long v) { return __uint_as_float((unsigned)(v >> 32)); }

__device__ __forceinline__ float tanh_fast(float x) {
    float y;
    asm("tanh.approx.f32 %0, %1;" : "=f"(y) : "f"(x));
    return y;
}
__device__ __forceinline__ float sigm(float x) { return 1.f / (1.f + expf(-x)); }

// ============================================================================
// Kernel A: persistent precompute. Grid=592 blocks x 128 threads (4 warps).
// Weights loaded ONCE per block (coalesced LDG + padded STS transpose), then
// a grid-stride loop over 32-token tiles:
//   GEMM1: h = x@W1^T + b1 -> LN -> exact GELU
//   GEMM2: pre = h@Wc1[:,4:]^T + bc1 ; bx = h@Wi^T + bi
// lane = token, warp = 16 output columns.
// ============================================================================
__global__ __launch_bounds__(128) void prep_kernel(
    const float* __restrict__ x, const float* __restrict__ W1, const float* __restrict__ b1,
    const float* __restrict__ ln_g, const float* __restrict__ ln_b,
    const float* __restrict__ Wi, const float* __restrict__ bi,
    const float* __restrict__ Wc1, const float* __restrict__ bc1)
{
    __shared__ __align__(16) float sW1[64 * 68];   // [k*68+j] = W1[j][k]  (pad 68)
    __shared__ __align__(16) float sWc1[64 * 68];  // [h*68+j] = Wc1[j][4+h]
    __shared__ __align__(16) float sWi[64 * 4];    // [h*4+i]  = Wi[i][h]
    __shared__ __align__(16) float sx[64 * 33];    // xs[k*33+t] / hs[h*33+t] / ps[j*33+t]
    __shared__ float2 sred[4][32];
    __shared__ float sb1[64], slng[64], slnb[64], sbc1[64], sbi[4];

    const int tid  = threadIdx.x;
    const int lane = tid & 31;
    const int wid  = tid >> 5;
    const int jb   = wid * 16;

    // ---- one-time weight load (coalesced LDG, padded STS transpose) ----
#pragma unroll
    for (int it = 0; it < 32; it++) {
        int idx = it * 128 + tid;          // 4096
        int j = idx >> 6, k = idx & 63;
        sW1[k * 68 + j]  = W1[idx];              // W1[j*64+k] == W1[idx]
        sWc1[k * 68 + j] = Wc1[j * 68 + 4 + k];
    }
#pragma unroll
    for (int it = 0; it < 2; it++) {
        int idx = it * 128 + tid;          // 256
        int h = idx >> 2, i = idx & 3;
        sWi[idx] = Wi[i * 64 + h];
    }
    if (tid < 64) {
        sb1[tid]  = b1[tid];
        slng[tid] = ln_g[tid];
        slnb[tid] = ln_b[tid];
        sbc1[tid] = bc1[tid];
        if (tid < 4) sbi[tid] = bi[tid];
    }
    __syncthreads();

    for (int tile = blockIdx.x; tile < NTILES; tile += PREP_GRID) {
        const int tokbase = tile * 32;
        const float* xg = x + (size_t)tokbase * 64;

        // ---- stage x transposed: xs[k][t] ----
#pragma unroll
        for (int it = 0; it < 4; it++) {
            int idx4 = (it * 128 + tid) * 4;     // 0..2044
            float4 v = *reinterpret_cast<const float4*>(xg + idx4);
            int t = idx4 >> 6, k = idx4 & 63;
            sx[k * 33 + t]       = v.x;
            sx[(k + 1) * 33 + t] = v.y;
            sx[(k + 2) * 33 + t] = v.z;
            sx[(k + 3) * 33 + t] = v.w;
        }
        __syncthreads();   // S1

        // ---- GEMM1 ----
        unsigned long long acc[8];
#pragma unroll
        for (int p = 0; p < 8; p++)
            acc[p] = pk2(sb1[jb + 2 * p], sb1[jb + 2 * p + 1]);

#pragma unroll 8
        for (int k = 0; k < 64; k++) {
            unsigned long long xk2 = dup2(sx[k * 33 + lane]);
            const ulonglong2* wp = reinterpret_cast<const ulonglong2*>(&sW1[k * 68 + jb]);
            ulonglong2 w0 = wp[0], w1 = wp[1], w2 = wp[2], w3 = wp[3];
            acc[0] = fma2(w0.x, xk2, acc[0]);
            acc[1] = fma2(w0.y, xk2, acc[1]);
            acc[2] = fma2(w1.x, xk2, acc[2]);
            acc[3] = fma2(w1.y, xk2, acc[3]);
            acc[4] = fma2(w2.x, xk2, acc[4]);
            acc[5] = fma2(w2.y, xk2, acc[5]);
            acc[6] = fma2(w3.x, xk2, acc[6]);
            acc[7] = fma2(w3.y, xk2, acc[7]);
        }

        // ---- LayerNorm partials ----
        float hv[16];
#pragma unroll
        for (int p = 0; p < 8; p++) { hv[2 * p] = lo2(acc[p]); hv[2 * p + 1] = hi2(acc[p]); }
        float s1v = 0.f, s2v = 0.f;
#pragma unroll
        for (int q = 0; q < 16; q++) { s1v += hv[q]; s2v = fmaf(hv[q], hv[q], s2v); }
        sred[wid][lane] = make_float2(s1v, s2v);
        __syncthreads();   // S2: GEMM1 sx reads done + sred visible

        float su = 0.f, sq = 0.f;
#pragma unroll
        for (int w = 0; w < 4; w++) { float2 r = sred[w][lane]; su += r.x; sq += r.y; }
        float mu   = su * (1.f / 64.f);
        float var  = fmaf(sq, 1.f / 64.f, -mu * mu);
        float rstd = rsqrtf(var + 1e-5f);

        // ---- normalize + exact GELU, stage hs into sx ----
#pragma unroll
        for (int q = 0; q < 16; q++) {
            int j = jb + q;
            float v  = fmaf((hv[q] - mu) * rstd, slng[j], slnb[j]);
            float ge = 0.5f * v * (1.f + erff(v * 0.70710678118654752f));
            sx[j * 33 + lane] = ge;
        }
        __syncthreads();   // S3

        // ---- GEMM2: pre ----
        unsigned long long pa[8];
#pragma unroll
        for (int p = 0; p < 8; p++)
            pa[p] = pk2(sbc1[jb + 2 * p], sbc1[jb + 2 * p + 1]);

#pragma unroll 8
        for (int h = 0; h < 64; h++) {
            unsigned long long h2 = dup2(sx[h * 33 + lane]);
            const ulonglong2* wp = reinterpret_cast<const ulonglong2*>(&sWc1[h * 68 + jb]);
            ulonglong2 w0 = wp[0], w1 = wp[1], w2 = wp[2], w3 = wp[3];
            pa[0] = fma2(w0.x, h2, pa[0]);
            pa[1] = fma2(w0.y, h2, pa[1]);
            pa[2] = fma2(w1.x, h2, pa[2]);
            pa[3] = fma2(w1.y, h2, pa[3]);
            pa[4] = fma2(w2.x, h2, pa[4]);
            pa[5] = fma2(w2.y, h2, pa[5]);
            pa[6] = fma2(w3.x, h2, pa[6]);
            pa[7] = fma2(w3.y, h2, pa[7]);
        }

        // ---- bx = h@Wi^T + bi (warp 0) ----
        if (wid == 0) {
            unsigned long long bxa0 = pk2(sbi[0], sbi[1]);
            unsigned long long bxa1 = pk2(sbi[2], sbi[3]);
#pragma unroll 8
            for (int h = 0; h < 64; h++) {
                unsigned long long h2 = dup2(sx[h * 33 + lane]);
                const ulonglong2 wiv = *reinterpret_cast<const ulonglong2*>(&sWi[h * 4]);
                bxa0 = fma2(wiv.x, h2, bxa0);
                bxa1 = fma2(wiv.y, h2, bxa1);
            }
            float4 bo = make_float4(lo2(bxa0), hi2(bxa0), lo2(bxa1), hi2(bxa1));
            *reinterpret_cast<float4*>(&g_bx[(size_t)(tokbase + lane) * 4]) = bo;
        }
        __syncthreads();   // S4: hs reads done

        // ---- stage pre transposed: ps[j][t] ----
#pragma unroll
        for (int p = 0; p < 8; p++) {
            int j = jb + 2 * p;
            sx[j * 33 + lane]       = lo2(pa[p]);
            sx[(j + 1) * 33 + lane] = hi2(pa[p]);
        }
        __syncthreads();   // S5

        // ---- coalesced float4 writeout of pre ----
        float* preg = g_pre + (size_t)tokbase * 64;
#pragma unroll
        for (int it = 0; it < 4; it++) {
            int idx4 = (it * 128 + tid) * 4;
            int t = idx4 >> 6, j = idx4 & 63;
            float4 v = make_float4(sx[j * 33 + t], sx[(j + 1) * 33 + t],
                                   sx[(j + 2) * 33 + t], sx[(j + 3) * 33 + t]);
            *reinterpret_cast<float4*>(preg + idx4) = v;
        }
        __syncthreads();   // S6: sx reads done before next tile's staging
    }
}

// ============================================================================
// Kernel B: sequential scan. One warp per batch; lane owns cols 2l,2l+1.
// Depth-8 register prefetch ring. Retimed recurrence: carry (sl, th) so the
// loop chain is th -> sl (1 fma) -> u -> gelu -> p -> butterfly -> tanh.
// bc2 folded into reduction init as bc2/32 (exact).
// ============================================================================
__global__ __launch_bounds__(32) void scan_kernel(
    const float* __restrict__ Wc1, const float* __restrict__ Wc2, const float* __restrict__ bc2,
    const float* __restrict__ corr_scale,
    const float* __restrict__ A_level, const float* __restrict__ A_trend,
    const float* __restrict__ A_gamma, const float* __restrict__ A_resid,
    const float* __restrict__ omega,
    float* __restrict__ out)
{
    const int b    = blockIdx.x;
    const int lane = threadIdx.x;
    const int j0   = lane * 2;

    float wS0[4], wS1[4], w20[4], w21[4], bc32[4];
#pragma unroll
    for (int i = 0; i < 4; i++) {
        wS0[i]  = __ldg(Wc1 + j0 * 68 + i);
        wS1[i]  = __ldg(Wc1 + (j0 + 1) * 68 + i);
        w20[i]  = __ldg(Wc2 + i * 64 + j0);
        w21[i]  = __ldg(Wc2 + i * 64 + j0 + 1);
        bc32[i] = __ldg(bc2 + i) * 0.03125f;   // /32, exact
    }
    const float cs = __ldg(corr_scale);
    const float a0 = sigm(__ldg(A_level)) * 0.15f + 0.85f;
    const float a1 = sigm(__ldg(A_trend)) * 0.25f + 0.7f;
    const float a2 = (sigm(__ldg(A_gamma)) * 0.2f + 0.8f) * cosf(__ldg(omega));
    const float a3 = sigm(__ldg(A_resid)) * 0.4f;
    const float acs0 = a0 * cs, acs1 = a1 * cs, acs2 = a2 * cs, acs3 = a3 * cs;

    const float* prep = g_pre + ((size_t)b * SS) * 64 + j0;
    const float* bxp  = g_bx  + ((size_t)b * SS) * 4;
    float* outp       = out   + ((size_t)b * SS) * 4;

    // carried state: v = s_lin(t-1), th = tanh-correction(t-1); zeros at t=0
    float v0 = 0.f, v1 = 0.f, v2 = 0.f, v3 = 0.f;
    float th0 = 0.f, th1 = 0.f, th2 = 0.f, th3 = 0.f;

    float2 prb[8];
    float4 bxb[8];
#pragma unroll
    for (int i = 0; i < 8; i++) {
        prb[i] = __ldcs(reinterpret_cast<const float2*>(prep + (size_t)i * 64));
        bxb[i] = __ldg(reinterpret_cast<const float4*>(bxp + (size_t)i * 4));
    }

    for (int tb = 0; tb < SS; tb += 8) {
#pragma unroll
        for (int u = 0; u < 8; u++) {
            const int t = tb + u;
            float2 pr = prb[u];
            float4 bx = bxb[u];

            // prefetch t+8 into this slot (issued early, consumed 8 iters later)
            int tp = t + 8;
            if (tp > SS - 1) tp = SS - 1;
            prb[u] = __ldcs(reinterpret_cast<const float2*>(prep + (size_t)tp * 64));
            bxb[u] = __ldg(reinterpret_cast<const float4*>(bxp + (size_t)tp * 4));

            // s_lin(t) = a*s(t-1) + bx = (a*v + bx) + (a*cs)*th
            float slb0 = fmaf(a0, v0, bx.x);
            float slb1 = fmaf(a1, v1, bx.y);
            float slb2 = fmaf(a2, v2, bx.z);
            float slb3 = fmaf(a3, v3, bx.w);
            float sl0 = fmaf(acs0, th0, slb0);
            float sl1 = fmaf(acs1, th1, slb1);
            float sl2 = fmaf(acs2, th2, slb2);
            float sl3 = fmaf(acs3, th3, slb3);

            // u = pre + sl @ Wc1[:, :4]^T   (tree form, depth 12)
            float ua0 = fmaf(sl1, wS0[1], fmaf(sl0, wS0[0], pr.x));
            float ub0 = fmaf(sl3, wS0[3], sl2 * wS0[2]);
            float uu0 = ua0 + ub0;
            float ua1 = fmaf(sl1, wS1[1], fmaf(sl0, wS1[0], pr.y));
            float ub1 = fmaf(sl3, wS1[3], sl2 * wS1[2]);
            float uu1 = ua1 + ub1;

            // fast GELU (tanh form); error only via x0.01 correction path
            float uh0 = 0.5f * uu0;
            float q0  = uu0 * uu0;
            float in0 = uu0 * fmaf(0.0356774081f, q0, 0.7978845608f);
            float g0  = fmaf(tanh_fast(in0), uh0, uh0);
            float uh1 = 0.5f * uu1;
            float q1  = uu1 * uu1;
            float in1 = uu1 * fmaf(0.0356774081f, q1, 0.7978845608f);
            float g1  = fmaf(tanh_fast(in1), uh1, uh1);

            // partial c, bc2/32 folded in
            float p0 = fmaf(g0, w20[0], fmaf(g1, w21[0], bc32[0]));
            float p1 = fmaf(g0, w20[1], fmaf(g1, w21[1], bc32[1]));
            float p2 = fmaf(g0, w20[2], fmaf(g1, w21[2], bc32[2]));
            float p3 = fmaf(g0, w20[3], fmaf(g1, w21[3], bc32[3]));
#pragma unroll
            for (int off = 16; off; off >>= 1) {
                p0 += __shfl_xor_sync(0xffffffffu, p0, off);
                p1 += __shfl_xor_sync(0xffffffffu, p1, off);
                p2 += __shfl_xor_sync(0xffffffffu, p2, off);
                p3 += __shfl_xor_sync(0xffffffffu, p3, off);
            }
            float nth0 = tanh_fast(p0);
            float nth1 = tanh_fast(p1);
            float nth2 = tanh_fast(p2);
            float nth3 = tanh_fast(p3);

            // output s(t) = sl + cs*th(t)   (off the loop-carried chain)
            if (lane == 0) {
                float4 so = make_float4(fmaf(cs, nth0, sl0), fmaf(cs, nth1, sl1),
                                        fmaf(cs, nth2, sl2), fmaf(cs, nth3, sl3));
                *reinterpret_cast<float4*>(outp + (size_t)t * 4) = so;
            }

            v0 = sl0; v1 = sl1; v2 = sl2; v3 = sl3;
            th0 = nth0; th1 = nth1; th2 = nth2; th3 = nth3;
        }
    }
}

extern "C" void kernel_launch(void* const* d_in, const int* in_sizes, int n_in,
                              void* d_out, int out_size)
{
    const float* x          = (const float*)d_in[0];
    const float* W1         = (const float*)d_in[1];
    const float* b1         = (const float*)d_in[2];
    const float* ln_g       = (const float*)d_in[3];
    const float* ln_b       = (const float*)d_in[4];
    const float* Wi         = (const float*)d_in[5];
    const float* bi         = (const float*)d_in[6];
    const float* Wc1        = (const float*)d_in[7];
    const float* bc1        = (const float*)d_in[8];
    const float* Wc2        = (const float*)d_in[9];
    const float* bc2        = (const float*)d_in[10];
    const float* corr_scale = (const float*)d_in[11];
    const float* A_level    = (const float*)d_in[12];
    const float* A_trend    = (const float*)d_in[13];
    const float* A_gamma    = (const float*)d_in[14];
    const float* A_resid    = (const float*)d_in[15];
    const float* omega      = (const float*)d_in[16];
    float* out = (float*)d_out;

    prep_kernel<<<PREP_GRID, 128>>>(x, W1, b1, ln_g, ln_b, Wi, bi, Wc1, bc1);
    scan_kernel<<<BB, 32>>>(Wc1, Wc2, bc2, corr_scale,
                            A_level, A_trend, A_gamma, A_resid, omega, out);
}

// round 3
// speedup vs baseline: 1.8718x; 1.1216x over previous
#include <cuda_runtime.h>
#include <math.h>

#define BB 512
#define SS 1024
#define TILE_T 64
#define NT64 ((BB * SS) / TILE_T)   // 8192 tiles of 64 tokens
#define PREP_GRID 592
#define SMEM_DYN ((2 * 64 * 68 + 64 * 65) * 4)   // 51456 bytes

// Scratch (static device globals — allocation-guard-safe)
__device__ float g_pre[BB * SS * 64];   // 134 MB: h @ Wc1[:,4:]^T + bc1
__device__ float g_bx[BB * SS * 4];     // 8 MB:  h @ Wi^T + bi
__device__ unsigned int g_tilectr;

// ---------- f32x2 helpers (Blackwell FFMA2 path) ----------
__device__ __forceinline__ unsigned long long pk2(float lo, float hi) {
    unsigned long long r;
    asm("mov.b64 %0, {%1,%2};" : "=l"(r) : "f"(lo), "f"(hi));
    return r;
}
__device__ __forceinline__ unsigned long long dup2(float x) {
    unsigned long long r;
    asm("mov.b64 %0, {%1,%1};" : "=l"(r) : "f"(x));
    return r;
}
__device__ __forceinline__ unsigned long long fma2(unsigned long long a,
                                                   unsigned long long b,
                                                   unsigned long long c) {
    unsigned long long d;
    asm("fma.rn.f32x2 %0, %1, %2, %3;" : "=l"(d) : "l"(a), "l"(b), "l"(c));
    return d;
}
__device__ __forceinline__ float lo2(unsigned long long v) { return __uint_as_float((unsigned)v); }
__device__ __forceinline__ float hi2(unsigned long long v) { return __uint_as_float((unsigned)(v >> 32)); }

__device__ __forceinline__ float tanh_fast(float x) {
    float y;
    asm("tanh.approx.f32 %0, %1;" : "=f"(y) : "f"(x));
    return y;
}
__device__ __forceinline__ float sigm(float x) { return 1.f / (1.f + expf(-x)); }
__device__ __forceinline__ float gelu_fast(float u) {
    float uh = 0.5f * u;
    float q  = u * u;
    float in = u * fmaf(0.0356774081f, q, 0.7978845608f);
    return fmaf(tanh_fast(in), uh, uh);
}

__global__ void init_ctr() { g_tilectr = PREP_GRID; }

// ============================================================================
// Kernel A: persistent precompute, atomic tile scheduler.
// Block = 128 threads (4 warps); tile = 64 tokens. Thread handles tokens
// (lane, lane+32) for its warp's 16 output columns. Weights loaded once per
// block (coalesced + padded transpose). Next tile's x prefetched into
// registers mid-tile so the staging barrier never waits on DRAM.
// ============================================================================
__global__ __launch_bounds__(128) void prep_kernel(
    const float* __restrict__ x, const float* __restrict__ W1, const float* __restrict__ b1,
    const float* __restrict__ ln_g, const float* __restrict__ ln_b,
    const float* __restrict__ Wi, const float* __restrict__ bi,
    const float* __restrict__ Wc1, const float* __restrict__ bc1)
{
    extern __shared__ float dyn[];
    float* sW1  = dyn;                 // [k*68+j] = W1[j][k]
    float* sWc1 = dyn + 64 * 68;       // [h*68+j] = Wc1[j][4+h]
    float* sx   = dyn + 2 * 64 * 68;   // 64x65: xs[k*65+t] / hs / ps

    __shared__ unsigned long long sWiP[2][64];   // [p][h] = (Wi[2p][h], Wi[2p+1][h])
    __shared__ float4 sred[4][32];
    __shared__ float sb1[64], slng[64], slnb[64], sbc1[64], sbi[4];
    __shared__ int s_next;

    const int tid  = threadIdx.x;
    const int lane = tid & 31;
    const int wid  = tid >> 5;
    const int jb   = wid * 16;

    // ---- one-time weight load ----
#pragma unroll
    for (int it = 0; it < 32; it++) {
        int idx = it * 128 + tid;          // 4096
        int j = idx >> 6, k = idx & 63;
        sW1[k * 68 + j]  = W1[idx];
        sWc1[k * 68 + j] = Wc1[j * 68 + 4 + k];
    }
    {
        int h = tid & 63, p = tid >> 6;
        sWiP[p][h] = pk2(Wi[(2 * p) * 64 + h], Wi[(2 * p + 1) * 64 + h]);
    }
    if (tid < 64) {
        sb1[tid]  = b1[tid];
        slng[tid] = ln_g[tid];
        slnb[tid] = ln_b[tid];
        sbc1[tid] = bc1[tid];
        if (tid < 4) sbi[tid] = bi[tid];
    }
    __syncthreads();

    int tile = blockIdx.x;
    float4 xr[8];
    {
        const float* xg = x + (size_t)tile * (TILE_T * 64);
#pragma unroll
        for (int it = 0; it < 8; it++)
            xr[it] = *reinterpret_cast<const float4*>(xg + (it * 128 + tid) * 4);
    }

    while (tile < NT64) {
        // ---- stage x from prefetch regs: sx[k][t] ----
#pragma unroll
        for (int it = 0; it < 8; it++) {
            int e = (it * 128 + tid) * 4;
            int t = e >> 6, k = e & 63;
            sx[k * 65 + t]       = xr[it].x;
            sx[(k + 1) * 65 + t] = xr[it].y;
            sx[(k + 2) * 65 + t] = xr[it].z;
            sx[(k + 3) * 65 + t] = xr[it].w;
        }
        __syncthreads();   // B1
        if (tid == 0) s_next = (int)atomicAdd(&g_tilectr, 1u);

        // ---- GEMM1: 2 tokens per thread ----
        unsigned long long aA[8], aB[8];
#pragma unroll
        for (int p = 0; p < 8; p++) {
            unsigned long long bv = pk2(sb1[jb + 2 * p], sb1[jb + 2 * p + 1]);
            aA[p] = bv; aB[p] = bv;
        }
#pragma unroll 4
        for (int k = 0; k < 64; k++) {
            unsigned long long xa2 = dup2(sx[k * 65 + lane]);
            unsigned long long xb2 = dup2(sx[k * 65 + 32 + lane]);
            const ulonglong2* wp = reinterpret_cast<const ulonglong2*>(&sW1[k * 68 + jb]);
            ulonglong2 w0 = wp[0], w1 = wp[1], w2 = wp[2], w3 = wp[3];
            aA[0] = fma2(w0.x, xa2, aA[0]);  aB[0] = fma2(w0.x, xb2, aB[0]);
            aA[1] = fma2(w0.y, xa2, aA[1]);  aB[1] = fma2(w0.y, xb2, aB[1]);
            aA[2] = fma2(w1.x, xa2, aA[2]);  aB[2] = fma2(w1.x, xb2, aB[2]);
            aA[3] = fma2(w1.y, xa2, aA[3]);  aB[3] = fma2(w1.y, xb2, aB[3]);
            aA[4] = fma2(w2.x, xa2, aA[4]);  aB[4] = fma2(w2.x, xb2, aB[4]);
            aA[5] = fma2(w2.y, xa2, aA[5]);  aB[5] = fma2(w2.y, xb2, aB[5]);
            aA[6] = fma2(w3.x, xa2, aA[6]);  aB[6] = fma2(w3.x, xb2, aB[6]);
            aA[7] = fma2(w3.y, xa2, aA[7]);  aB[7] = fma2(w3.y, xb2, aB[7]);
        }

        // ---- LN partials ----
        float hA[16], hB[16];
#pragma unroll
        for (int p = 0; p < 8; p++) {
            hA[2 * p] = lo2(aA[p]); hA[2 * p + 1] = hi2(aA[p]);
            hB[2 * p] = lo2(aB[p]); hB[2 * p + 1] = hi2(aB[p]);
        }
        float s1a = 0.f, s2a = 0.f, s1b = 0.f, s2b = 0.f;
#pragma unroll
        for (int q = 0; q < 16; q++) {
            s1a += hA[q]; s2a = fmaf(hA[q], hA[q], s2a);
            s1b += hB[q]; s2b = fmaf(hB[q], hB[q], s2b);
        }
        sred[wid][lane] = make_float4(s1a, s2a, s1b, s2b);
        __syncthreads();   // B2: GEMM1 sx reads done + partials visible

        // ---- prefetch next tile's x (covered by ~2000 cyc of work below) ----
        const int ntile = s_next;
        if (ntile < NT64) {
            const float* xg = x + (size_t)ntile * (TILE_T * 64);
#pragma unroll
            for (int it = 0; it < 8; it++)
                xr[it] = *reinterpret_cast<const float4*>(xg + (it * 128 + tid) * 4);
        }

        // ---- LN finalize + exact GELU, stage h into sx ----
        float suA = 0.f, sqA = 0.f, suB = 0.f, sqB = 0.f;
#pragma unroll
        for (int w = 0; w < 4; w++) {
            float4 r = sred[w][lane];
            suA += r.x; sqA += r.y; suB += r.z; sqB += r.w;
        }
        float muA = suA * (1.f / 64.f);
        float rsA = rsqrtf(fmaf(sqA, 1.f / 64.f, -muA * muA) + 1e-5f);
        float muB = suB * (1.f / 64.f);
        float rsB = rsqrtf(fmaf(sqB, 1.f / 64.f, -muB * muB) + 1e-5f);
#pragma unroll
        for (int q = 0; q < 16; q++) {
            int j = jb + q;
            float vA = fmaf((hA[q] - muA) * rsA, slng[j], slnb[j]);
            float vB = fmaf((hB[q] - muB) * rsB, slng[j], slnb[j]);
            sx[j * 65 + lane]      = 0.5f * vA * (1.f + erff(vA * 0.70710678118654752f));
            sx[j * 65 + 32 + lane] = 0.5f * vB * (1.f + erff(vB * 0.70710678118654752f));
        }
        __syncthreads();   // B3

        // ---- GEMM2: pre ----
        unsigned long long pA[8], pB[8];
#pragma unroll
        for (int p = 0; p < 8; p++) {
            unsigned long long bv = pk2(sbc1[jb + 2 * p], sbc1[jb + 2 * p + 1]);
            pA[p] = bv; pB[p] = bv;
        }
#pragma unroll 4
        for (int h = 0; h < 64; h++) {
            unsigned long long ha2 = dup2(sx[h * 65 + lane]);
            unsigned long long hb2 = dup2(sx[h * 65 + 32 + lane]);
            const ulonglong2* wp = reinterpret_cast<const ulonglong2*>(&sWc1[h * 68 + jb]);
            ulonglong2 w0 = wp[0], w1 = wp[1], w2 = wp[2], w3 = wp[3];
            pA[0] = fma2(w0.x, ha2, pA[0]);  pB[0] = fma2(w0.x, hb2, pB[0]);
            pA[1] = fma2(w0.y, ha2, pA[1]);  pB[1] = fma2(w0.y, hb2, pB[1]);
            pA[2] = fma2(w1.x, ha2, pA[2]);  pB[2] = fma2(w1.x, hb2, pB[2]);
            pA[3] = fma2(w1.y, ha2, pA[3]);  pB[3] = fma2(w1.y, hb2, pB[3]);
            pA[4] = fma2(w2.x, ha2, pA[4]);  pB[4] = fma2(w2.x, hb2, pB[4]);
            pA[5] = fma2(w2.y, ha2, pA[5]);  pB[5] = fma2(w2.y, hb2, pB[5]);
            pA[6] = fma2(w3.x, ha2, pA[6]);  pB[6] = fma2(w3.x, hb2, pB[6]);
            pA[7] = fma2(w3.y, ha2, pA[7]);  pB[7] = fma2(w3.y, hb2, pB[7]);
        }

        // ---- bx: evenly split (warp pair -> col pair, warp parity -> token half) ----
        {
            const int p = wid >> 1;
            const int t = ((wid & 1) << 5) + lane;
            unsigned long long acc = pk2(sbi[2 * p], sbi[2 * p + 1]);
#pragma unroll 8
            for (int h = 0; h < 64; h++)
                acc = fma2(sWiP[p][h], dup2(sx[h * 65 + t]), acc);
            *reinterpret_cast<float2*>(&g_bx[(size_t)(tile * TILE_T + t) * 4 + 2 * p]) =
                make_float2(lo2(acc), hi2(acc));
        }
        __syncthreads();   // B4: h reads done

        // ---- stage pre transposed ----
#pragma unroll
        for (int q = 0; q < 8; q++) {
            int j = jb + 2 * q;
            sx[j * 65 + lane]            = lo2(pA[q]);
            sx[(j + 1) * 65 + lane]      = hi2(pA[q]);
            sx[j * 65 + 32 + lane]       = lo2(pB[q]);
            sx[(j + 1) * 65 + 32 + lane] = hi2(pB[q]);
        }
        __syncthreads();   // B5

        // ---- coalesced float4 writeout ----
        float* preg = g_pre + (size_t)tile * (TILE_T * 64);
#pragma unroll
        for (int it = 0; it < 8; it++) {
            int e = (it * 128 + tid) * 4;
            int t = e >> 6, j = e & 63;
            float4 v = make_float4(sx[j * 65 + t], sx[(j + 1) * 65 + t],
                                   sx[(j + 2) * 65 + t], sx[(j + 3) * 65 + t]);
            *reinterpret_cast<float4*>(preg + e) = v;
        }
        __syncthreads();   // B6: sx reads done before next staging
        tile = ntile;
    }
}

// ============================================================================
// Kernel B: sequential scan. 16 lanes per batch, 2 batches per warp, each
// lane owns 4 MLP columns. Butterfly reduce = 4 levels. Depth-8 prefetch
// ring. Retimed recurrence (carry sl, th). bc2 folded as bc2/16.
// ============================================================================
__global__ __launch_bounds__(32) void scan_kernel(
    const float* __restrict__ Wc1, const float* __restrict__ Wc2, const float* __restrict__ bc2,
    const float* __restrict__ corr_scale,
    const float* __restrict__ A_level, const float* __restrict__ A_trend,
    const float* __restrict__ A_gamma, const float* __restrict__ A_resid,
    const float* __restrict__ omega,
    float* __restrict__ out)
{
    const int lane = threadIdx.x;
    const int half = lane >> 4;
    const int g    = lane & 15;
    const int b    = blockIdx.x * 2 + half;
    const int j0   = g * 4;

    float wS[4][4], w2[4][4], bc16[4];
#pragma unroll
    for (int c = 0; c < 4; c++)
#pragma unroll
        for (int i = 0; i < 4; i++) {
            wS[c][i] = __ldg(Wc1 + (j0 + c) * 68 + i);
            w2[i][c] = __ldg(Wc2 + i * 64 + j0 + c);
        }
#pragma unroll
    for (int i = 0; i < 4; i++) bc16[i] = __ldg(bc2 + i) * 0.0625f;   // /16, exact

    const float cs = __ldg(corr_scale);
    const float a0 = sigm(__ldg(A_level)) * 0.15f + 0.85f;
    const float a1 = sigm(__ldg(A_trend)) * 0.25f + 0.7f;
    const float a2 = (sigm(__ldg(A_gamma)) * 0.2f + 0.8f) * cosf(__ldg(omega));
    const float a3 = sigm(__ldg(A_resid)) * 0.4f;
    const float acs0 = a0 * cs, acs1 = a1 * cs, acs2 = a2 * cs, acs3 = a3 * cs;

    const float* prep = g_pre + ((size_t)b * SS) * 64 + j0;
    const float* bxp  = g_bx  + ((size_t)b * SS) * 4;
    float* outp       = out   + ((size_t)b * SS) * 4;

    float v0 = 0.f, v1 = 0.f, v2 = 0.f, v3 = 0.f;
    float th0 = 0.f, th1 = 0.f, th2 = 0.f, th3 = 0.f;

    float4 prb[8], bxb[8];
#pragma unroll
    for (int i = 0; i < 8; i++) {
        prb[i] = __ldcs(reinterpret_cast<const float4*>(prep + (size_t)i * 64));
        bxb[i] = __ldg(reinterpret_cast<const float4*>(bxp + (size_t)i * 4));
    }

    for (int tb = 0; tb < SS; tb += 8) {
#pragma unroll
        for (int u = 0; u < 8; u++) {
            const int t = tb + u;
            float4 pr = prb[u];
            float4 bx = bxb[u];

            int tp = t + 8;
            if (tp > SS - 1) tp = SS - 1;
            prb[u] = __ldcs(reinterpret_cast<const float4*>(prep + (size_t)tp * 64));
            bxb[u] = __ldg(reinterpret_cast<const float4*>(bxp + (size_t)tp * 4));

            // s_lin(t)
            float sl0 = fmaf(acs0, th0, fmaf(a0, v0, bx.x));
            float sl1 = fmaf(acs1, th1, fmaf(a1, v1, bx.y));
            float sl2 = fmaf(acs2, th2, fmaf(a2, v2, bx.z));
            float sl3 = fmaf(acs3, th3, fmaf(a3, v3, bx.w));

            // u_c = pre_c + sl @ Wc1[:, :4]^T  (tree form), then fast GELU
            float uu0 = fmaf(sl1, wS[0][1], fmaf(sl0, wS[0][0], pr.x)) + fmaf(sl3, wS[0][3], sl2 * wS[0][2]);
            float uu1 = fmaf(sl1, wS[1][1], fmaf(sl0, wS[1][0], pr.y)) + fmaf(sl3, wS[1][3], sl2 * wS[1][2]);
            float uu2 = fmaf(sl1, wS[2][1], fmaf(sl0, wS[2][0], pr.z)) + fmaf(sl3, wS[2][3], sl2 * wS[2][2]);
            float uu3 = fmaf(sl1, wS[3][1], fmaf(sl0, wS[3][0], pr.w)) + fmaf(sl3, wS[3][3], sl2 * wS[3][2]);
            float g0 = gelu_fast(uu0);
            float g1 = gelu_fast(uu1);
            float g2 = gelu_fast(uu2);
            float g3 = gelu_fast(uu3);

            // per-lane partial of c (4 columns), bc2/16 folded in
            float p0 = fmaf(g1, w2[0][1], fmaf(g0, w2[0][0], bc16[0])) + fmaf(g3, w2[0][3], g2 * w2[0][2]);
            float p1 = fmaf(g1, w2[1][1], fmaf(g0, w2[1][0], bc16[1])) + fmaf(g3, w2[1][3], g2 * w2[1][2]);
            float p2 = fmaf(g1, w2[2][1], fmaf(g0, w2[2][0], bc16[2])) + fmaf(g3, w2[2][3], g2 * w2[2][2]);
            float p3 = fmaf(g1, w2[3][1], fmaf(g0, w2[3][0], bc16[3])) + fmaf(g3, w2[3][3], g2 * w2[3][2]);

            // 4-level butterfly within each 16-lane group
#pragma unroll
            for (int off = 8; off; off >>= 1) {
                p0 += __shfl_xor_sync(0xffffffffu, p0, off);
                p1 += __shfl_xor_sync(0xffffffffu, p1, off);
                p2 += __shfl_xor_sync(0xffffffffu, p2, off);
                p3 += __shfl_xor_sync(0xffffffffu, p3, off);
            }
            float nth0 = tanh_fast(p0);
            float nth1 = tanh_fast(p1);
            float nth2 = tanh_fast(p2);
            float nth3 = tanh_fast(p3);

            if (g == 0) {
                float4 so = make_float4(fmaf(cs, nth0, sl0), fmaf(cs, nth1, sl1),
                                        fmaf(cs, nth2, sl2), fmaf(cs, nth3, sl3));
                *reinterpret_cast<float4*>(outp + (size_t)t * 4) = so;
            }

            v0 = sl0; v1 = sl1; v2 = sl2; v3 = sl3;
            th0 = nth0; th1 = nth1; th2 = nth2; th3 = nth3;
        }
    }
}

extern "C" void kernel_launch(void* const* d_in, const int* in_sizes, int n_in,
                              void* d_out, int out_size)
{
    const float* x          = (const float*)d_in[0];
    const float* W1         = (const float*)d_in[1];
    const float* b1         = (const float*)d_in[2];
    const float* ln_g       = (const float*)d_in[3];
    const float* ln_b       = (const float*)d_in[4];
    const float* Wi         = (const float*)d_in[5];
    const float* bi         = (const float*)d_in[6];
    const float* Wc1        = (const float*)d_in[7];
    const float* bc1        = (const float*)d_in[8];
    const float* Wc2        = (const float*)d_in[9];
    const float* bc2        = (const float*)d_in[10];
    const float* corr_scale = (const float*)d_in[11];
    const float* A_level    = (const float*)d_in[12];
    const float* A_trend    = (const float*)d_in[13];
    const float* A_gamma    = (const float*)d_in[14];
    const float* A_resid    = (const float*)d_in[15];
    const float* omega      = (const float*)d_in[16];
    float* out = (float*)d_out;

    cudaFuncSetAttribute(prep_kernel, cudaFuncAttributeMaxDynamicSharedMemorySize, SMEM_DYN);
    init_ctr<<<1, 1>>>();
    prep_kernel<<<PREP_GRID, 128, SMEM_DYN>>>(x, W1, b1, ln_g, ln_b, Wi, bi, Wc1, bc1);
    scan_kernel<<<BB / 2, 32>>>(Wc1, Wc2, bc2, corr_scale,
                                A_level, A_trend, A_gamma, A_resid, omega, out);
}

// round 5
// speedup vs baseline: 2.4814x; 1.3257x over previous
#include <cuda_runtime.h>
#include <cuda_bf16.h>
#include <math.h>
#include <stdint.h>

#define BB 512
#define SS 1024
#define TILE_T 64
#define NTILE ((BB * SS) / TILE_T)   // 8192 tiles of 64 tokens
#define PREP_GRID 444                // 148 SMs * 3 blocks (55KB smem each)

// bf16 smem tiles: 64 rows x 72 bf16 (144B stride = 36 u32) -> conflict-free frags
#define STR32 36
#define TBYTES (64 * 72 * 2)         // 9216
#define OFF_AH  0
#define OFF_AL  (TBYTES)
#define OFF_B1H (2 * TBYTES)
#define OFF_B1L (3 * TBYTES)
#define OFF_B2H (4 * TBYTES)
#define OFF_B2L (5 * TBYTES)
#define SMEM_DYN (6 * TBYTES)        // 55296 bytes

// Scratch (static device globals — allocation-guard-safe)
__device__ float g_pre[BB * SS * 64];   // 134 MB
__device__ float g_bx[BB * SS * 4];     // 8 MB

__device__ __forceinline__ float tanh_fast(float x) {
    float y;
    asm("tanh.approx.f32 %0, %1;" : "=f"(y) : "f"(x));
    return y;
}
__device__ __forceinline__ float sigm(float x) { return 1.f / (1.f + expf(-x)); }

__device__ __forceinline__ uint32_t pack_bf2(float a, float b) {
    __nv_bfloat162 v = __halves2bfloat162(__float2bfloat16(a), __float2bfloat16(b));
    return *reinterpret_cast<uint32_t*>(&v);
}
__device__ __forceinline__ void split_bf(float v, float& hi, float& lo) {
    hi = __bfloat162float(__float2bfloat16(v));
    lo = v - hi;
}

// mma.sync m16n8k16 bf16 (base ISA, compiles under compute_103)
__device__ __forceinline__ void mma16816(float d[4], uint32_t a0, uint32_t a1,
                                         uint32_t a2, uint32_t a3,
                                         uint32_t b0, uint32_t b1) {
    asm volatile(
        "mma.sync.aligned.m16n8k16.row.col.f32.bf16.bf16.f32 "
        "{%0,%1,%2,%3}, {%4,%5,%6,%7}, {%8,%9}, {%0,%1,%2,%3};"
        : "+f"(d[0]), "+f"(d[1]), "+f"(d[2]), "+f"(d[3])
        : "r"(a0), "r"(a1), "r"(a2), "r"(a3), "r"(b0), "r"(b1));
}

// One 16x64 output tile: D += A(16x64) @ B^T(64x64), 3-product split precision.
// A rows = warp band (warp_row + {g, g+8}); B rows = output cols.
__device__ __forceinline__ void gemm_band(
    float d[8][4], const uint32_t* __restrict__ Ah, const uint32_t* __restrict__ Al,
    const uint32_t* __restrict__ Bh, const uint32_t* __restrict__ Bl,
    int warp_row, int g, int t)
{
#pragma unroll
    for (int ks = 0; ks < 4; ks++) {
        const int aw = (warp_row + g) * STR32 + 8 * ks + t;
        const uint32_t ah0 = Ah[aw],               ah1 = Ah[aw + 8 * STR32];
        const uint32_t ah2 = Ah[aw + 4],           ah3 = Ah[aw + 8 * STR32 + 4];
        const uint32_t al0 = Al[aw],               al1 = Al[aw + 8 * STR32];
        const uint32_t al2 = Al[aw + 4],           al3 = Al[aw + 8 * STR32 + 4];
#pragma unroll
        for (int nt = 0; nt < 8; nt++) {
            const int bw = (nt * 8 + g) * STR32 + 8 * ks + t;
            const uint32_t bh0 = Bh[bw], bh1 = Bh[bw + 4];
            const uint32_t bl0 = Bl[bw], bl1 = Bl[bw + 4];
            mma16816(d[nt], ah0, ah1, ah2, ah3, bh0, bh1);
            mma16816(d[nt], al0, al1, al2, al3, bh0, bh1);
            mma16816(d[nt], ah0, ah1, ah2, ah3, bl0, bl1);
        }
    }
}

// ============================================================================
// Kernel A: persistent precompute via warp-level bf16 HMMA.
// Block = 128 threads (4 warps); tile = 64 tokens. Warp w owns rows
// w*16..w*16+15 x all 64 cols. GEMM1 -> b1+LN+exact GELU+bx (on fragments,
// quad-shuffle row reductions) -> restage h (bf16 hi/lo) -> GEMM2 -> pre.
// ============================================================================
__global__ __launch_bounds__(128) void prep_kernel(
    const float* __restrict__ x, const float* __restrict__ W1, const float* __restrict__ b1,
    const float* __restrict__ ln_g, const float* __restrict__ ln_b,
    const float* __restrict__ Wi, const float* __restrict__ bi,
    const float* __restrict__ Wc1, const float* __restrict__ bc1)
{
    extern __shared__ __align__(16) char sm[];
    __shared__ float sWi[4][64], sb1[64], slng[64], slnb[64], sbc1[64], sbi[4];

    __nv_bfloat16* hA  = reinterpret_cast<__nv_bfloat16*>(sm + OFF_AH);
    __nv_bfloat16* lA  = reinterpret_cast<__nv_bfloat16*>(sm + OFF_AL);
    __nv_bfloat16* hB1 = reinterpret_cast<__nv_bfloat16*>(sm + OFF_B1H);
    __nv_bfloat16* lB1 = reinterpret_cast<__nv_bfloat16*>(sm + OFF_B1L);
    __nv_bfloat16* hB2 = reinterpret_cast<__nv_bfloat16*>(sm + OFF_B2H);
    __nv_bfloat16* lB2 = reinterpret_cast<__nv_bfloat16*>(sm + OFF_B2L);
    const uint32_t* Ah32  = reinterpret_cast<const uint32_t*>(sm + OFF_AH);
    const uint32_t* Al32  = reinterpret_cast<const uint32_t*>(sm + OFF_AL);
    const uint32_t* B1h32 = reinterpret_cast<const uint32_t*>(sm + OFF_B1H);
    const uint32_t* B1l32 = reinterpret_cast<const uint32_t*>(sm + OFF_B1L);
    const uint32_t* B2h32 = reinterpret_cast<const uint32_t*>(sm + OFF_B2H);
    const uint32_t* B2l32 = reinterpret_cast<const uint32_t*>(sm + OFF_B2L);

    const int tid  = threadIdx.x;
    const int lane = tid & 31;
    const int wid  = tid >> 5;
    const int g    = lane >> 2;    // fragment row group 0..7
    const int t    = lane & 3;     // fragment quad id 0..3
    const int wrow = wid * 16;

    // ---- one-time weight staging (bf16 hi/lo splits) ----
#pragma unroll
    for (int it = 0; it < 32; it++) {
        int idx = it * 128 + tid;            // 4096
        int j = idx >> 6, k = idx & 63;
        float w1v = W1[idx];                 // W1[j][k]
        float wcv = Wc1[j * 68 + 4 + k];     // Wc1[j][4+k]
        float h1, l1, h2, l2;
        split_bf(w1v, h1, l1);
        split_bf(wcv, h2, l2);
        hB1[j * 72 + k] = __float2bfloat16(h1);
        lB1[j * 72 + k] = __float2bfloat16(l1);
        hB2[j * 72 + k] = __float2bfloat16(h2);
        lB2[j * 72 + k] = __float2bfloat16(l2);
    }
#pragma unroll
    for (int q = tid; q < 256; q += 128) sWi[q >> 6][q & 63] = Wi[q];
    if (tid < 64) {
        sb1[tid]  = b1[tid];
        slng[tid] = ln_g[tid];
        slnb[tid] = ln_b[tid];
        sbc1[tid] = bc1[tid];
        if (tid < 4) sbi[tid] = bi[tid];
    }
    __syncthreads();

    for (int tile = blockIdx.x; tile < NTILE; tile += PREP_GRID) {
        const int tokbase = tile * TILE_T;
        const float4* xg4 = reinterpret_cast<const float4*>(x + (size_t)tokbase * 64);

        // ---- stage x (bf16 hi/lo, padded rows) ----
#pragma unroll
        for (int it = 0; it < 8; it++) {
            int idx = it * 128 + tid;        // float4 index 0..1023
            float4 v = xg4[idx];
            int row = idx >> 4, c = (idx & 15) * 4;
            float h0, l0, h1, l1, h2, l2, h3, l3;
            split_bf(v.x, h0, l0); split_bf(v.y, h1, l1);
            split_bf(v.z, h2, l2); split_bf(v.w, h3, l3);
            uint32_t* dh = const_cast<uint32_t*>(Ah32) + row * STR32 + (c >> 1);
            uint32_t* dl = const_cast<uint32_t*>(Al32) + row * STR32 + (c >> 1);
            dh[0] = pack_bf2(h0, h1); dh[1] = pack_bf2(h2, h3);
            dl[0] = pack_bf2(l0, l1); dl[1] = pack_bf2(l2, l3);
        }
        __syncthreads();   // B1

        // ---- GEMM1: d = x @ W1^T ----
        float d[8][4];
#pragma unroll
        for (int nt = 0; nt < 8; nt++)
#pragma unroll
            for (int q = 0; q < 4; q++) d[nt][q] = 0.f;
        gemm_band(d, Ah32, Al32, B1h32, B1l32, wrow, g, t);

        // ---- epilogue: +b1, LN (quad reduce), exact GELU ----
        float sA = 0.f, sB = 0.f;
#pragma unroll
        for (int nt = 0; nt < 8; nt++) {
            const int c0 = nt * 8 + 2 * t;
            d[nt][0] += sb1[c0];     d[nt][1] += sb1[c0 + 1];
            d[nt][2] += sb1[c0];     d[nt][3] += sb1[c0 + 1];
            sA += d[nt][0] + d[nt][1];
            sB += d[nt][2] + d[nt][3];
        }
        sA += __shfl_xor_sync(0xffffffffu, sA, 1);
        sA += __shfl_xor_sync(0xffffffffu, sA, 2);
        sB += __shfl_xor_sync(0xffffffffu, sB, 1);
        sB += __shfl_xor_sync(0xffffffffu, sB, 2);
        const float muA = sA * (1.f / 64.f), muB = sB * (1.f / 64.f);
        float qA = 0.f, qB = 0.f;
#pragma unroll
        for (int nt = 0; nt < 8; nt++) {
            float d0 = d[nt][0] - muA, d1 = d[nt][1] - muA;
            float d2 = d[nt][2] - muB, d3 = d[nt][3] - muB;
            qA = fmaf(d0, d0, fmaf(d1, d1, qA));
            qB = fmaf(d2, d2, fmaf(d3, d3, qB));
        }
        qA += __shfl_xor_sync(0xffffffffu, qA, 1);
        qA += __shfl_xor_sync(0xffffffffu, qA, 2);
        qB += __shfl_xor_sync(0xffffffffu, qB, 1);
        qB += __shfl_xor_sync(0xffffffffu, qB, 2);
        const float rsA = rsqrtf(qA * (1.f / 64.f) + 1e-5f);
        const float rsB = rsqrtf(qB * (1.f / 64.f) + 1e-5f);
#pragma unroll
        for (int nt = 0; nt < 8; nt++) {
            const int c0 = nt * 8 + 2 * t;
            const float g0 = slng[c0], g1 = slng[c0 + 1];
            const float o0 = slnb[c0], o1 = slnb[c0 + 1];
            float v0 = fmaf((d[nt][0] - muA) * rsA, g0, o0);
            float v1 = fmaf((d[nt][1] - muA) * rsA, g1, o1);
            float v2 = fmaf((d[nt][2] - muB) * rsB, g0, o0);
            float v3 = fmaf((d[nt][3] - muB) * rsB, g1, o1);
            d[nt][0] = 0.5f * v0 * (1.f + erff(v0 * 0.70710678118654752f));
            d[nt][1] = 0.5f * v1 * (1.f + erff(v1 * 0.70710678118654752f));
            d[nt][2] = 0.5f * v2 * (1.f + erff(v2 * 0.70710678118654752f));
            d[nt][3] = 0.5f * v3 * (1.f + erff(v3 * 0.70710678118654752f));
        }

        // ---- bx = h @ Wi^T + bi (quad reduce; t==0 writes both rows) ----
        {
            float pA[4] = {0.f, 0.f, 0.f, 0.f}, pB[4] = {0.f, 0.f, 0.f, 0.f};
#pragma unroll
            for (int nt = 0; nt < 8; nt++) {
                const int c0 = nt * 8 + 2 * t;
#pragma unroll
                for (int i = 0; i < 4; i++) {
                    const float w0 = sWi[i][c0], w1 = sWi[i][c0 + 1];
                    pA[i] = fmaf(d[nt][0], w0, fmaf(d[nt][1], w1, pA[i]));
                    pB[i] = fmaf(d[nt][2], w0, fmaf(d[nt][3], w1, pB[i]));
                }
            }
#pragma unroll
            for (int i = 0; i < 4; i++) {
                pA[i] += __shfl_xor_sync(0xffffffffu, pA[i], 1);
                pA[i] += __shfl_xor_sync(0xffffffffu, pA[i], 2);
                pB[i] += __shfl_xor_sync(0xffffffffu, pB[i], 1);
                pB[i] += __shfl_xor_sync(0xffffffffu, pB[i], 2);
            }
            if (t == 0) {
                const int rA = tokbase + wrow + g;
                *reinterpret_cast<float4*>(g_bx + (size_t)rA * 4) =
                    make_float4(pA[0] + sbi[0], pA[1] + sbi[1], pA[2] + sbi[2], pA[3] + sbi[3]);
                *reinterpret_cast<float4*>(g_bx + (size_t)(rA + 8) * 4) =
                    make_float4(pB[0] + sbi[0], pB[1] + sbi[1], pB[2] + sbi[2], pB[3] + sbi[3]);
            }
        }
        __syncthreads();   // B2: all GEMM1 A-reads done before restage

        // ---- restage h (bf16 hi/lo) into A tiles ----
#pragma unroll
        for (int nt = 0; nt < 8; nt++) {
            const int w0 = (wrow + g) * STR32 + 4 * nt + t;
            const int w1 = (wrow + g + 8) * STR32 + 4 * nt + t;
            float h0, l0, h1, l1, h2, l2, h3, l3;
            split_bf(d[nt][0], h0, l0); split_bf(d[nt][1], h1, l1);
            split_bf(d[nt][2], h2, l2); split_bf(d[nt][3], h3, l3);
            const_cast<uint32_t*>(Ah32)[w0] = pack_bf2(h0, h1);
            const_cast<uint32_t*>(Al32)[w0] = pack_bf2(l0, l1);
            const_cast<uint32_t*>(Ah32)[w1] = pack_bf2(h2, h3);
            const_cast<uint32_t*>(Al32)[w1] = pack_bf2(l2, l3);
        }
        __syncthreads();   // B3

        // ---- GEMM2: pre = h @ Wc1[:,4:]^T + bc1 ----
#pragma unroll
        for (int nt = 0; nt < 8; nt++)
#pragma unroll
            for (int q = 0; q < 4; q++) d[nt][q] = 0.f;
        gemm_band(d, Ah32, Al32, B2h32, B2l32, wrow, g, t);

        {
            float* preA = g_pre + (size_t)(tokbase + wrow + g) * 64;
            float* preB = preA + 8 * 64;
#pragma unroll
            for (int nt = 0; nt < 8; nt++) {
                const int c0 = nt * 8 + 2 * t;
                const float bc0 = sbc1[c0], bc1v = sbc1[c0 + 1];
                *reinterpret_cast<float2*>(preA + c0) = make_float2(d[nt][0] + bc0, d[nt][1] + bc1v);
                *reinterpret_cast<float2*>(preB + c0) = make_float2(d[nt][2] + bc0, d[nt][3] + bc1v);
            }
        }
        __syncthreads();   // B4: GEMM2 A-reads done before next tile staging
    }
}

// ============================================================================
// Kernel B: sequential scan (verbatim R3). 16 lanes per batch, 2 batches per
// warp, lane owns 4 MLP columns; 4-level butterfly; depth-8 prefetch ring.
// ============================================================================
__global__ __launch_bounds__(32) void scan_kernel(
    const float* __restrict__ Wc1, const float* __restrict__ Wc2, const float* __restrict__ bc2,
    const float* __restrict__ corr_scale,
    const float* __restrict__ A_level, const float* __restrict__ A_trend,
    const float* __restrict__ A_gamma, const float* __restrict__ A_resid,
    const float* __restrict__ omega,
    float* __restrict__ out)
{
    const int lane = threadIdx.x;
    const int half = lane >> 4;
    const int g    = lane & 15;
    const int b    = blockIdx.x * 2 + half;
    const int j0   = g * 4;

    float wS[4][4], w2[4][4], bc16[4];
#pragma unroll
    for (int c = 0; c < 4; c++)
#pragma unroll
        for (int i = 0; i < 4; i++) {
            wS[c][i] = __ldg(Wc1 + (j0 + c) * 68 + i);
            w2[i][c] = __ldg(Wc2 + i * 64 + j0 + c);
        }
#pragma unroll
    for (int i = 0; i < 4; i++) bc16[i] = __ldg(bc2 + i) * 0.0625f;

    const float cs = __ldg(corr_scale);
    const float a0 = sigm(__ldg(A_level)) * 0.15f + 0.85f;
    const float a1 = sigm(__ldg(A_trend)) * 0.25f + 0.7f;
    const float a2 = (sigm(__ldg(A_gamma)) * 0.2f + 0.8f) * cosf(__ldg(omega));
    const float a3 = sigm(__ldg(A_resid)) * 0.4f;
    const float acs0 = a0 * cs, acs1 = a1 * cs, acs2 = a2 * cs, acs3 = a3 * cs;

    const float* prep = g_pre + ((size_t)b * SS) * 64 + j0;
    const float* bxp  = g_bx  + ((size_t)b * SS) * 4;
    float* outp       = out   + ((size_t)b * SS) * 4;

    float v0 = 0.f, v1 = 0.f, v2 = 0.f, v3 = 0.f;
    float th0 = 0.f, th1 = 0.f, th2 = 0.f, th3 = 0.f;

    float4 prb[8], bxb[8];
#pragma unroll
    for (int i = 0; i < 8; i++) {
        prb[i] = __ldcs(reinterpret_cast<const float4*>(prep + (size_t)i * 64));
        bxb[i] = __ldg(reinterpret_cast<const float4*>(bxp + (size_t)i * 4));
    }

    for (int tb = 0; tb < SS; tb += 8) {
#pragma unroll
        for (int u = 0; u < 8; u++) {
            const int t = tb + u;
            float4 pr = prb[u];
            float4 bx = bxb[u];

            int tp = t + 8;
            if (tp > SS - 1) tp = SS - 1;
            prb[u] = __ldcs(reinterpret_cast<const float4*>(prep + (size_t)tp * 64));
            bxb[u] = __ldg(reinterpret_cast<const float4*>(bxp + (size_t)tp * 4));

            float sl0 = fmaf(acs0, th0, fmaf(a0, v0, bx.x));
            float sl1 = fmaf(acs1, th1, fmaf(a1, v1, bx.y));
            float sl2 = fmaf(acs2, th2, fmaf(a2, v2, bx.z));
            float sl3 = fmaf(acs3, th3, fmaf(a3, v3, bx.w));

            float uu0 = fmaf(sl1, wS[0][1], fmaf(sl0, wS[0][0], pr.x)) + fmaf(sl3, wS[0][3], sl2 * wS[0][2]);
            float uu1 = fmaf(sl1, wS[1][1], fmaf(sl0, wS[1][0], pr.y)) + fmaf(sl3, wS[1][3], sl2 * wS[1][2]);
            float uu2 = fmaf(sl1, wS[2][1], fmaf(sl0, wS[2][0], pr.z)) + fmaf(sl3, wS[2][3], sl2 * wS[2][2]);
            float uu3 = fmaf(sl1, wS[3][1], fmaf(sl0, wS[3][0], pr.w)) + fmaf(sl3, wS[3][3], sl2 * wS[3][2]);

            float uh0 = 0.5f * uu0, qq0 = uu0 * uu0;
            float g0 = fmaf(tanh_fast(uu0 * fmaf(0.0356774081f, qq0, 0.7978845608f)), uh0, uh0);
            float uh1 = 0.5f * uu1, qq1 = uu1 * uu1;
            float g1 = fmaf(tanh_fast(uu1 * fmaf(0.0356774081f, qq1, 0.7978845608f)), uh1, uh1);
            float uh2 = 0.5f * uu2, qq2 = uu2 * uu2;
            float g2 = fmaf(tanh_fast(uu2 * fmaf(0.0356774081f, qq2, 0.7978845608f)), uh2, uh2);
            float uh3 = 0.5f * uu3, qq3 = uu3 * uu3;
            float g3 = fmaf(tanh_fast(uu3 * fmaf(0.0356774081f, qq3, 0.7978845608f)), uh3, uh3);

            float p0 = fmaf(g1, w2[0][1], fmaf(g0, w2[0][0], bc16[0])) + fmaf(g3, w2[0][3], g2 * w2[0][2]);
            float p1 = fmaf(g1, w2[1][1], fmaf(g0, w2[1][0], bc16[1])) + fmaf(g3, w2[1][3], g2 * w2[1][2]);
            float p2 = fmaf(g1, w2[2][1], fmaf(g0, w2[2][0], bc16[2])) + fmaf(g3, w2[2][3], g2 * w2[2][2]);
            float p3 = fmaf(g1, w2[3][1], fmaf(g0, w2[3][0], bc16[3])) + fmaf(g3, w2[3][3], g2 * w2[3][2]);

#pragma unroll
            for (int off = 8; off; off >>= 1) {
                p0 += __shfl_xor_sync(0xffffffffu, p0, off);
                p1 += __shfl_xor_sync(0xffffffffu, p1, off);
                p2 += __shfl_xor_sync(0xffffffffu, p2, off);
                p3 += __shfl_xor_sync(0xffffffffu, p3, off);
            }
            float nth0 = tanh_fast(p0);
            float nth1 = tanh_fast(p1);
            float nth2 = tanh_fast(p2);
            float nth3 = tanh_fast(p3);

            if (g == 0) {
                float4 so = make_float4(fmaf(cs, nth0, sl0), fmaf(cs, nth1, sl1),
                                        fmaf(cs, nth2, sl2), fmaf(cs, nth3, sl3));
                *reinterpret_cast<float4*>(outp + (size_t)t * 4) = so;
            }

            v0 = sl0; v1 = sl1; v2 = sl2; v3 = sl3;
            th0 = nth0; th1 = nth1; th2 = nth2; th3 = nth3;
        }
    }
}

extern "C" void kernel_launch(void* const* d_in, const int* in_sizes, int n_in,
                              void* d_out, int out_size)
{
    const float* x          = (const float*)d_in[0];
    const float* W1         = (const float*)d_in[1];
    const float* b1         = (const float*)d_in[2];
    const float* ln_g       = (const float*)d_in[3];
    const float* ln_b       = (const float*)d_in[4];
    const float* Wi         = (const float*)d_in[5];
    const float* bi         = (const float*)d_in[6];
    const float* Wc1        = (const float*)d_in[7];
    const float* bc1        = (const float*)d_in[8];
    const float* Wc2        = (const float*)d_in[9];
    const float* bc2        = (const float*)d_in[10];
    const float* corr_scale = (const float*)d_in[11];
    const float* A_level    = (const float*)d_in[12];
    const float* A_trend    = (const float*)d_in[13];
    const float* A_gamma    = (const float*)d_in[14];
    const float* A_resid    = (const float*)d_in[15];
    const float* omega      = (const float*)d_in[16];
    float* out = (float*)d_out;

    cudaFuncSetAttribute(prep_kernel, cudaFuncAttributeMaxDynamicSharedMemorySize, SMEM_DYN);
    prep_kernel<<<PREP_GRID, 128, SMEM_DYN>>>(x, W1, b1, ln_g, ln_b, Wi, bi, Wc1, bc1);
    scan_kernel<<<BB / 2, 32>>>(Wc1, Wc2, bc2, corr_scale,
                                A_level, A_trend, A_gamma, A_resid, omega, out);
}

// round 6
// speedup vs baseline: 3.5544x; 1.4324x over previous
#include <cuda_runtime.h>
#include <cuda_bf16.h>
#include <math.h>
#include <stdint.h>

#define BB 512
#define SS 1024
#define TILE_T 64
#define NTILE ((BB * SS) / TILE_T)   // 8192 tiles of 64 tokens
#define PREP_GRID 444                // 148 SMs * 3 blocks (55KB smem each)

#define CHUNKS 8
#define CHLEN (SS / CHUNKS)          // 128
#define WARM 224                     // 0.925^224 ~ 2.6e-8 forgetting

// bf16 smem tiles: 64 rows x 72 bf16 (144B stride = 36 u32) -> conflict-free frags
#define STR32 36
#define TBYTES (64 * 72 * 2)         // 9216
#define OFF_AH  0
#define OFF_AL  (TBYTES)
#define OFF_B1H (2 * TBYTES)
#define OFF_B1L (3 * TBYTES)
#define OFF_B2H (4 * TBYTES)
#define OFF_B2L (5 * TBYTES)
#define SMEM_DYN (6 * TBYTES)        // 55296 bytes

// Scratch (static device globals — allocation-guard-safe)
__device__ uint32_t g_pre_bf[BB * SS * 32];   // 67 MB: bf16x2-packed pre
__device__ float g_bx[BB * SS * 4];           // 8 MB

__device__ __forceinline__ float tanh_fast(float x) {
    float y;
    asm("tanh.approx.f32 %0, %1;" : "=f"(y) : "f"(x));
    return y;
}
__device__ __forceinline__ float sigm(float x) { return 1.f / (1.f + expf(-x)); }

__device__ __forceinline__ uint32_t pack_bf2(float a, float b) {
    __nv_bfloat162 v = __halves2bfloat162(__float2bfloat16(a), __float2bfloat16(b));
    return *reinterpret_cast<uint32_t*>(&v);
}
__device__ __forceinline__ void split_bf(float v, float& hi, float& lo) {
    hi = __bfloat162float(__float2bfloat16(v));
    lo = v - hi;
}

// mma.sync m16n8k16 bf16 (base ISA, compiles under compute_103)
__device__ __forceinline__ void mma16816(float d[4], uint32_t a0, uint32_t a1,
                                         uint32_t a2, uint32_t a3,
                                         uint32_t b0, uint32_t b1) {
    asm volatile(
        "mma.sync.aligned.m16n8k16.row.col.f32.bf16.bf16.f32 "
        "{%0,%1,%2,%3}, {%4,%5,%6,%7}, {%8,%9}, {%0,%1,%2,%3};"
        : "+f"(d[0]), "+f"(d[1]), "+f"(d[2]), "+f"(d[3])
        : "r"(a0), "r"(a1), "r"(a2), "r"(a3), "r"(b0), "r"(b1));
}

// One 16x64 output tile: D += A(16x64) @ B^T(64x64), 3-product split precision.
__device__ __forceinline__ void gemm_band(
    float d[8][4], const uint32_t* __restrict__ Ah, const uint32_t* __restrict__ Al,
    const uint32_t* __restrict__ Bh, const uint32_t* __restrict__ Bl,
    int warp_row, int g, int t)
{
#pragma unroll
    for (int ks = 0; ks < 4; ks++) {
        const int aw = (warp_row + g) * STR32 + 8 * ks + t;
        const uint32_t ah0 = Ah[aw],               ah1 = Ah[aw + 8 * STR32];
        const uint32_t ah2 = Ah[aw + 4],           ah3 = Ah[aw + 8 * STR32 + 4];
        const uint32_t al0 = Al[aw],               al1 = Al[aw + 8 * STR32];
        const uint32_t al2 = Al[aw + 4],           al3 = Al[aw + 8 * STR32 + 4];
#pragma unroll
        for (int nt = 0; nt < 8; nt++) {
            const int bw = (nt * 8 + g) * STR32 + 8 * ks + t;
            const uint32_t bh0 = Bh[bw], bh1 = Bh[bw + 4];
            const uint32_t bl0 = Bl[bw], bl1 = Bl[bw + 4];
            mma16816(d[nt], ah0, ah1, ah2, ah3, bh0, bh1);
            mma16816(d[nt], al0, al1, al2, al3, bh0, bh1);
            mma16816(d[nt], ah0, ah1, ah2, ah3, bl0, bl1);
        }
    }
}

// ============================================================================
// Kernel A: persistent precompute via warp-level bf16 HMMA (R5 structure).
// pre now stored as packed bf16 (errors damped x corr_scale in the scan).
// ============================================================================
__global__ __launch_bounds__(128) void prep_kernel(
    const float* __restrict__ x, const float* __restrict__ W1, const float* __restrict__ b1,
    const float* __restrict__ ln_g, const float* __restrict__ ln_b,
    const float* __restrict__ Wi, const float* __restrict__ bi,
    const float* __restrict__ Wc1, const float* __restrict__ bc1)
{
    extern __shared__ __align__(16) char sm[];
    __shared__ float sWi[4][64], sb1[64], slng[64], slnb[64], sbc1[64], sbi[4];

    __nv_bfloat16* hB1 = reinterpret_cast<__nv_bfloat16*>(sm + OFF_B1H);
    __nv_bfloat16* lB1 = reinterpret_cast<__nv_bfloat16*>(sm + OFF_B1L);
    __nv_bfloat16* hB2 = reinterpret_cast<__nv_bfloat16*>(sm + OFF_B2H);
    __nv_bfloat16* lB2 = reinterpret_cast<__nv_bfloat16*>(sm + OFF_B2L);
    const uint32_t* Ah32  = reinterpret_cast<const uint32_t*>(sm + OFF_AH);
    const uint32_t* Al32  = reinterpret_cast<const uint32_t*>(sm + OFF_AL);
    const uint32_t* B1h32 = reinterpret_cast<const uint32_t*>(sm + OFF_B1H);
    const uint32_t* B1l32 = reinterpret_cast<const uint32_t*>(sm + OFF_B1L);
    const uint32_t* B2h32 = reinterpret_cast<const uint32_t*>(sm + OFF_B2H);
    const uint32_t* B2l32 = reinterpret_cast<const uint32_t*>(sm + OFF_B2L);

    const int tid  = threadIdx.x;
    const int lane = tid & 31;
    const int wid  = tid >> 5;
    const int g    = lane >> 2;
    const int t    = lane & 3;
    const int wrow = wid * 16;

    // ---- one-time weight staging (bf16 hi/lo splits) ----
#pragma unroll
    for (int it = 0; it < 32; it++) {
        int idx = it * 128 + tid;
        int j = idx >> 6, k = idx & 63;
        float w1v = W1[idx];
        float wcv = Wc1[j * 68 + 4 + k];
        float h1, l1, h2, l2;
        split_bf(w1v, h1, l1);
        split_bf(wcv, h2, l2);
        hB1[j * 72 + k] = __float2bfloat16(h1);
        lB1[j * 72 + k] = __float2bfloat16(l1);
        hB2[j * 72 + k] = __float2bfloat16(h2);
        lB2[j * 72 + k] = __float2bfloat16(l2);
    }
#pragma unroll
    for (int q = tid; q < 256; q += 128) sWi[q >> 6][q & 63] = Wi[q];
    if (tid < 64) {
        sb1[tid]  = b1[tid];
        slng[tid] = ln_g[tid];
        slnb[tid] = ln_b[tid];
        sbc1[tid] = bc1[tid];
        if (tid < 4) sbi[tid] = bi[tid];
    }
    __syncthreads();

    for (int tile = blockIdx.x; tile < NTILE; tile += PREP_GRID) {
        const int tokbase = tile * TILE_T;
        const float4* xg4 = reinterpret_cast<const float4*>(x + (size_t)tokbase * 64);

        // ---- stage x (bf16 hi/lo, padded rows) ----
#pragma unroll
        for (int it = 0; it < 8; it++) {
            int idx = it * 128 + tid;
            float4 v = xg4[idx];
            int row = idx >> 4, c = (idx & 15) * 4;
            float h0, l0, h1, l1, h2, l2, h3, l3;
            split_bf(v.x, h0, l0); split_bf(v.y, h1, l1);
            split_bf(v.z, h2, l2); split_bf(v.w, h3, l3);
            uint32_t* dh = const_cast<uint32_t*>(Ah32) + row * STR32 + (c >> 1);
            uint32_t* dl = const_cast<uint32_t*>(Al32) + row * STR32 + (c >> 1);
            dh[0] = pack_bf2(h0, h1); dh[1] = pack_bf2(h2, h3);
            dl[0] = pack_bf2(l0, l1); dl[1] = pack_bf2(l2, l3);
        }
        __syncthreads();   // B1

        // ---- GEMM1: d = x @ W1^T ----
        float d[8][4];
#pragma unroll
        for (int nt = 0; nt < 8; nt++)
#pragma unroll
            for (int q = 0; q < 4; q++) d[nt][q] = 0.f;
        gemm_band(d, Ah32, Al32, B1h32, B1l32, wrow, g, t);

        // ---- epilogue: +b1, LN (quad reduce), exact GELU ----
        float sA = 0.f, sB = 0.f;
#pragma unroll
        for (int nt = 0; nt < 8; nt++) {
            const int c0 = nt * 8 + 2 * t;
            d[nt][0] += sb1[c0];     d[nt][1] += sb1[c0 + 1];
            d[nt][2] += sb1[c0];     d[nt][3] += sb1[c0 + 1];
            sA += d[nt][0] + d[nt][1];
            sB += d[nt][2] + d[nt][3];
        }
        sA += __shfl_xor_sync(0xffffffffu, sA, 1);
        sA += __shfl_xor_sync(0xffffffffu, sA, 2);
        sB += __shfl_xor_sync(0xffffffffu, sB, 1);
        sB += __shfl_xor_sync(0xffffffffu, sB, 2);
        const float muA = sA * (1.f / 64.f), muB = sB * (1.f / 64.f);
        float qA = 0.f, qB = 0.f;
#pragma unroll
        for (int nt = 0; nt < 8; nt++) {
            float d0 = d[nt][0] - muA, d1 = d[nt][1] - muA;
            float d2 = d[nt][2] - muB, d3 = d[nt][3] - muB;
            qA = fmaf(d0, d0, fmaf(d1, d1, qA));
            qB = fmaf(d2, d2, fmaf(d3, d3, qB));
        }
        qA += __shfl_xor_sync(0xffffffffu, qA, 1);
        qA += __shfl_xor_sync(0xffffffffu, qA, 2);
        qB += __shfl_xor_sync(0xffffffffu, qB, 1);
        qB += __shfl_xor_sync(0xffffffffu, qB, 2);
        const float rsA = rsqrtf(qA * (1.f / 64.f) + 1e-5f);
        const float rsB = rsqrtf(qB * (1.f / 64.f) + 1e-5f);
#pragma unroll
        for (int nt = 0; nt < 8; nt++) {
            const int c0 = nt * 8 + 2 * t;
            const float g0 = slng[c0], g1 = slng[c0 + 1];
            const float o0 = slnb[c0], o1 = slnb[c0 + 1];
            float v0 = fmaf((d[nt][0] - muA) * rsA, g0, o0);
            float v1 = fmaf((d[nt][1] - muA) * rsA, g1, o1);
            float v2 = fmaf((d[nt][2] - muB) * rsB, g0, o0);
            float v3 = fmaf((d[nt][3] - muB) * rsB, g1, o1);
            d[nt][0] = 0.5f * v0 * (1.f + erff(v0 * 0.70710678118654752f));
            d[nt][1] = 0.5f * v1 * (1.f + erff(v1 * 0.70710678118654752f));
            d[nt][2] = 0.5f * v2 * (1.f + erff(v2 * 0.70710678118654752f));
            d[nt][3] = 0.5f * v3 * (1.f + erff(v3 * 0.70710678118654752f));
        }

        // ---- bx = h @ Wi^T + bi (quad reduce; t==0 writes both rows) ----
        {
            float pA[4] = {0.f, 0.f, 0.f, 0.f}, pB[4] = {0.f, 0.f, 0.f, 0.f};
#pragma unroll
            for (int nt = 0; nt < 8; nt++) {
                const int c0 = nt * 8 + 2 * t;
#pragma unroll
                for (int i = 0; i < 4; i++) {
                    const float w0 = sWi[i][c0], w1 = sWi[i][c0 + 1];
                    pA[i] = fmaf(d[nt][0], w0, fmaf(d[nt][1], w1, pA[i]));
                    pB[i] = fmaf(d[nt][2], w0, fmaf(d[nt][3], w1, pB[i]));
                }
            }
#pragma unroll
            for (int i = 0; i < 4; i++) {
                pA[i] += __shfl_xor_sync(0xffffffffu, pA[i], 1);
                pA[i] += __shfl_xor_sync(0xffffffffu, pA[i], 2);
                pB[i] += __shfl_xor_sync(0xffffffffu, pB[i], 1);
                pB[i] += __shfl_xor_sync(0xffffffffu, pB[i], 2);
            }
            if (t == 0) {
                const int rA = tokbase + wrow + g;
                *reinterpret_cast<float4*>(g_bx + (size_t)rA * 4) =
                    make_float4(pA[0] + sbi[0], pA[1] + sbi[1], pA[2] + sbi[2], pA[3] + sbi[3]);
                *reinterpret_cast<float4*>(g_bx + (size_t)(rA + 8) * 4) =
                    make_float4(pB[0] + sbi[0], pB[1] + sbi[1], pB[2] + sbi[2], pB[3] + sbi[3]);
            }
        }
        __syncthreads();   // B2

        // ---- restage h (bf16 hi/lo) into A tiles ----
#pragma unroll
        for (int nt = 0; nt < 8; nt++) {
            const int w0 = (wrow + g) * STR32 + 4 * nt + t;
            const int w1 = (wrow + g + 8) * STR32 + 4 * nt + t;
            float h0, l0, h1, l1, h2, l2, h3, l3;
            split_bf(d[nt][0], h0, l0); split_bf(d[nt][1], h1, l1);
            split_bf(d[nt][2], h2, l2); split_bf(d[nt][3], h3, l3);
            const_cast<uint32_t*>(Ah32)[w0] = pack_bf2(h0, h1);
            const_cast<uint32_t*>(Al32)[w0] = pack_bf2(l0, l1);
            const_cast<uint32_t*>(Ah32)[w1] = pack_bf2(h2, h3);
            const_cast<uint32_t*>(Al32)[w1] = pack_bf2(l2, l3);
        }
        __syncthreads();   // B3

        // ---- GEMM2: pre = h @ Wc1[:,4:]^T + bc1 -> bf16 packed ----
#pragma unroll
        for (int nt = 0; nt < 8; nt++)
#pragma unroll
            for (int q = 0; q < 4; q++) d[nt][q] = 0.f;
        gemm_band(d, Ah32, Al32, B2h32, B2l32, wrow, g, t);

        {
            uint32_t* preA = g_pre_bf + (size_t)(tokbase + wrow + g) * 32;
            uint32_t* preB = preA + 8 * 32;
#pragma unroll
            for (int nt = 0; nt < 8; nt++) {
                const int c0 = nt * 8 + 2 * t;
                const float bc0 = sbc1[c0], bc1v = sbc1[c0 + 1];
                preA[nt * 4 + t] = pack_bf2(d[nt][0] + bc0, d[nt][1] + bc1v);
                preB[nt * 4 + t] = pack_bf2(d[nt][2] + bc0, d[nt][3] + bc1v);
            }
        }
        __syncthreads();   // B4
    }
}

// ============================================================================
// Kernel B: CHUNKED sequential scan. grid = (BB/2, CHUNKS). Each block scans
// 2 batches over one 128-token chunk, warming up WARM=224 steps from zero
// state (a_max = 0.925 -> truncation ~1e-7). 16 lanes/batch, lane owns 4 MLP
// cols; 4-level butterfly; depth-8 prefetch ring; bf16 pre.
// ============================================================================
__global__ __launch_bounds__(32) void scan_kernel(
    const float* __restrict__ Wc1, const float* __restrict__ Wc2, const float* __restrict__ bc2,
    const float* __restrict__ corr_scale,
    const float* __restrict__ A_level, const float* __restrict__ A_trend,
    const float* __restrict__ A_gamma, const float* __restrict__ A_resid,
    const float* __restrict__ omega,
    float* __restrict__ out)
{
    const int lane = threadIdx.x;
    const int half = lane >> 4;
    const int g    = lane & 15;
    const int b    = blockIdx.x * 2 + half;
    const int j0   = g * 4;

    const int outbase = blockIdx.y * CHLEN;
    int start = outbase - WARM;
    if (start < 0) start = 0;
    const int end = outbase + CHLEN;

    float wS[4][4], w2[4][4], bc16[4];
#pragma unroll
    for (int c = 0; c < 4; c++)
#pragma unroll
        for (int i = 0; i < 4; i++) {
            wS[c][i] = __ldg(Wc1 + (j0 + c) * 68 + i);
            w2[i][c] = __ldg(Wc2 + i * 64 + j0 + c);
        }
#pragma unroll
    for (int i = 0; i < 4; i++) bc16[i] = __ldg(bc2 + i) * 0.0625f;

    const float cs = __ldg(corr_scale);
    const float a0 = sigm(__ldg(A_level)) * 0.15f + 0.85f;
    const float a1 = sigm(__ldg(A_trend)) * 0.25f + 0.7f;
    const float a2 = (sigm(__ldg(A_gamma)) * 0.2f + 0.8f) * cosf(__ldg(omega));
    const float a3 = sigm(__ldg(A_resid)) * 0.4f;
    const float acs0 = a0 * cs, acs1 = a1 * cs, acs2 = a2 * cs, acs3 = a3 * cs;

    // bf16 pre: 32 u32 per token; lane g reads uint2 #g = its 4 cols
    const uint2* prw = reinterpret_cast<const uint2*>(g_pre_bf + (size_t)b * SS * 32) + g;
    const float* bxp = g_bx + ((size_t)b * SS) * 4;
    float* outp      = out  + ((size_t)b * SS) * 4;

    float v0 = 0.f, v1 = 0.f, v2 = 0.f, v3 = 0.f;
    float th0 = 0.f, th1 = 0.f, th2 = 0.f, th3 = 0.f;

    uint2 prb[8];
    float4 bxb[8];
#pragma unroll
    for (int i = 0; i < 8; i++) {
        prb[i] = __ldcs(prw + (size_t)(start + i) * 16);
        bxb[i] = __ldg(reinterpret_cast<const float4*>(bxp + (size_t)(start + i) * 4));
    }

    for (int tb = start; tb < end; tb += 8) {
#pragma unroll
        for (int u = 0; u < 8; u++) {
            const int t = tb + u;
            uint2 pru = prb[u];
            float4 bx = bxb[u];

            int tp = t + 8;
            if (tp > SS - 1) tp = SS - 1;
            prb[u] = __ldcs(prw + (size_t)tp * 16);
            bxb[u] = __ldg(reinterpret_cast<const float4*>(bxp + (size_t)tp * 4));

            float2 f01 = __bfloat1622float2(*reinterpret_cast<__nv_bfloat162*>(&pru.x));
            float2 f23 = __bfloat1622float2(*reinterpret_cast<__nv_bfloat162*>(&pru.y));

            float sl0 = fmaf(acs0, th0, fmaf(a0, v0, bx.x));
            float sl1 = fmaf(acs1, th1, fmaf(a1, v1, bx.y));
            float sl2 = fmaf(acs2, th2, fmaf(a2, v2, bx.z));
            float sl3 = fmaf(acs3, th3, fmaf(a3, v3, bx.w));

            float uu0 = fmaf(sl1, wS[0][1], fmaf(sl0, wS[0][0], f01.x)) + fmaf(sl3, wS[0][3], sl2 * wS[0][2]);
            float uu1 = fmaf(sl1, wS[1][1], fmaf(sl0, wS[1][0], f01.y)) + fmaf(sl3, wS[1][3], sl2 * wS[1][2]);
            float uu2 = fmaf(sl1, wS[2][1], fmaf(sl0, wS[2][0], f23.x)) + fmaf(sl3, wS[2][3], sl2 * wS[2][2]);
            float uu3 = fmaf(sl1, wS[3][1], fmaf(sl0, wS[3][0], f23.y)) + fmaf(sl3, wS[3][3], sl2 * wS[3][2]);

            float uh0 = 0.5f * uu0, qq0 = uu0 * uu0;
            float g0 = fmaf(tanh_fast(uu0 * fmaf(0.0356774081f, qq0, 0.7978845608f)), uh0, uh0);
            float uh1 = 0.5f * uu1, qq1 = uu1 * uu1;
            float g1 = fmaf(tanh_fast(uu1 * fmaf(0.0356774081f, qq1, 0.7978845608f)), uh1, uh1);
            float uh2 = 0.5f * uu2, qq2 = uu2 * uu2;
            float g2 = fmaf(tanh_fast(uu2 * fmaf(0.0356774081f, qq2, 0.7978845608f)), uh2, uh2);
            float uh3 = 0.5f * uu3, qq3 = uu3 * uu3;
            float g3 = fmaf(tanh_fast(uu3 * fmaf(0.0356774081f, qq3, 0.7978845608f)), uh3, uh3);

            float p0 = fmaf(g1, w2[0][1], fmaf(g0, w2[0][0], bc16[0])) + fmaf(g3, w2[0][3], g2 * w2[0][2]);
            float p1 = fmaf(g1, w2[1][1], fmaf(g0, w2[1][0], bc16[1])) + fmaf(g3, w2[1][3], g2 * w2[1][2]);
            float p2 = fmaf(g1, w2[2][1], fmaf(g0, w2[2][0], bc16[2])) + fmaf(g3, w2[2][3], g2 * w2[2][2]);
            float p3 = fmaf(g1, w2[3][1], fmaf(g0, w2[3][0], bc16[3])) + fmaf(g3, w2[3][3], g2 * w2[3][2]);

#pragma unroll
            for (int off = 8; off; off >>= 1) {
                p0 += __shfl_xor_sync(0xffffffffu, p0, off);
                p1 += __shfl_xor_sync(0xffffffffu, p1, off);
                p2 += __shfl_xor_sync(0xffffffffu, p2, off);
                p3 += __shfl_xor_sync(0xffffffffu, p3, off);
            }
            float nth0 = tanh_fast(p0);
            float nth1 = tanh_fast(p1);
            float nth2 = tanh_fast(p2);
            float nth3 = tanh_fast(p3);

            if ((g == 0) && (t >= outbase)) {
                float4 so = make_float4(fmaf(cs, nth0, sl0), fmaf(cs, nth1, sl1),
                                        fmaf(cs, nth2, sl2), fmaf(cs, nth3, sl3));
                *reinterpret_cast<float4*>(outp + (size_t)t * 4) = so;
            }

            v0 = sl0; v1 = sl1; v2 = sl2; v3 = sl3;
            th0 = nth0; th1 = nth1; th2 = nth2; th3 = nth3;
        }
    }
}

extern "C" void kernel_launch(void* const* d_in, const int* in_sizes, int n_in,
                              void* d_out, int out_size)
{
    const float* x          = (const float*)d_in[0];
    const float* W1         = (const float*)d_in[1];
    const float* b1         = (const float*)d_in[2];
    const float* ln_g       = (const float*)d_in[3];
    const float* ln_b       = (const float*)d_in[4];
    const float* Wi         = (const float*)d_in[5];
    const float* bi         = (const float*)d_in[6];
    const float* Wc1        = (const float*)d_in[7];
    const float* bc1        = (const float*)d_in[8];
    const float* Wc2        = (const float*)d_in[9];
    const float* bc2        = (const float*)d_in[10];
    const float* corr_scale = (const float*)d_in[11];
    const float* A_level    = (const float*)d_in[12];
    const float* A_trend    = (const float*)d_in[13];
    const float* A_gamma    = (const float*)d_in[14];
    const float* A_resid    = (const float*)d_in[15];
    const float* omega      = (const float*)d_in[16];
    float* out = (float*)d_out;

    cudaFuncSetAttribute(prep_kernel, cudaFuncAttributeMaxDynamicSharedMemorySize, SMEM_DYN);
    prep_kernel<<<PREP_GRID, 128, SMEM_DYN>>>(x, W1, b1, ln_g, ln_b, Wi, bi, Wc1, bc1);
    dim3 sgrid(BB / 2, CHUNKS);
    scan_kernel<<<sgrid, 32>>>(Wc1, Wc2, bc2, corr_scale,
                               A_level, A_trend, A_gamma, A_resid, omega, out);
}

// round 7
// speedup vs baseline: 3.8855x; 1.0932x over previous
#include <cuda_runtime.h>
#include <cuda_bf16.h>
#include <cuda_fp16.h>
#include <math.h>
#include <stdint.h>

#define BB 512
#define SS 1024
#define TILE_T 64
#define NTILE ((BB * SS) / TILE_T)   // 8192 tiles of 64 tokens
#define PREP_GRID 444                // 148 SMs * 3 blocks (55KB smem each)

#define CHUNKS 8
#define CHLEN (SS / CHUNKS)          // 128
#define WARM 160                     // 0.925^160 ~ 3.8e-6 forgetting

// bf16 smem tiles: 64 rows x 72 bf16 (144B stride = 36 u32) -> conflict-free frags
#define STR32 36
#define TBYTES (64 * 72 * 2)         // 9216
#define OFF_AH  0
#define OFF_AL  (TBYTES)
#define OFF_B1H (2 * TBYTES)
#define OFF_B1L (3 * TBYTES)
#define OFF_B2H (4 * TBYTES)
#define OFF_B2L (5 * TBYTES)
#define SMEM_DYN (6 * TBYTES)        // 55296 bytes

// Scratch (static device globals — allocation-guard-safe)
__device__ uint32_t g_pre_bf[BB * SS * 32];   // 67 MB: bf16x2-packed pre
__device__ float g_bx[BB * SS * 4];           // 8 MB

__device__ __forceinline__ float sigm(float x) { return 1.f / (1.f + expf(-x)); }

__device__ __forceinline__ uint32_t pack_bf2(float a, float b) {
    __nv_bfloat162 v = __halves2bfloat162(__float2bfloat16(a), __float2bfloat16(b));
    return *reinterpret_cast<uint32_t*>(&v);
}
__device__ __forceinline__ void split_bf(float v, float& hi, float& lo) {
    hi = __bfloat162float(__float2bfloat16(v));
    lo = v - hi;
}
__device__ __forceinline__ __half2 tanh2(__half2 x) {
    __half2 y;
    asm("tanh.approx.f16x2 %0, %1;"
        : "=r"(*reinterpret_cast<uint32_t*>(&y))
        : "r"(*reinterpret_cast<uint32_t*>(&x)));
    return y;
}
__device__ __forceinline__ __half2 shfl_xor_h2(__half2 v, int off) {
    uint32_t u = *reinterpret_cast<uint32_t*>(&v);
    u = __shfl_xor_sync(0xffffffffu, u, off);
    return *reinterpret_cast<__half2*>(&u);
}

// mma.sync m16n8k16 bf16 (base ISA, compiles under compute_103)
__device__ __forceinline__ void mma16816(float d[4], uint32_t a0, uint32_t a1,
                                         uint32_t a2, uint32_t a3,
                                         uint32_t b0, uint32_t b1) {
    asm volatile(
        "mma.sync.aligned.m16n8k16.row.col.f32.bf16.bf16.f32 "
        "{%0,%1,%2,%3}, {%4,%5,%6,%7}, {%8,%9}, {%0,%1,%2,%3};"
        : "+f"(d[0]), "+f"(d[1]), "+f"(d[2]), "+f"(d[3])
        : "r"(a0), "r"(a1), "r"(a2), "r"(a3), "r"(b0), "r"(b1));
}

// One 16x64 output tile: D += A(16x64) @ B^T(64x64), 3-product split precision.
__device__ __forceinline__ void gemm_band(
    float d[8][4], const uint32_t* __restrict__ Ah, const uint32_t* __restrict__ Al,
    const uint32_t* __restrict__ Bh, const uint32_t* __restrict__ Bl,
    int warp_row, int g, int t)
{
#pragma unroll
    for (int ks = 0; ks < 4; ks++) {
        const int aw = (warp_row + g) * STR32 + 8 * ks + t;
        const uint32_t ah0 = Ah[aw],               ah1 = Ah[aw + 8 * STR32];
        const uint32_t ah2 = Ah[aw + 4],           ah3 = Ah[aw + 8 * STR32 + 4];
        const uint32_t al0 = Al[aw],               al1 = Al[aw + 8 * STR32];
        const uint32_t al2 = Al[aw + 4],           al3 = Al[aw + 8 * STR32 + 4];
#pragma unroll
        for (int nt = 0; nt < 8; nt++) {
            const int bw = (nt * 8 + g) * STR32 + 8 * ks + t;
            const uint32_t bh0 = Bh[bw], bh1 = Bh[bw + 4];
            const uint32_t bl0 = Bl[bw], bl1 = Bl[bw + 4];
            mma16816(d[nt], ah0, ah1, ah2, ah3, bh0, bh1);
            mma16816(d[nt], al0, al1, al2, al3, bh0, bh1);
            mma16816(d[nt], ah0, ah1, ah2, ah3, bl0, bl1);
        }
    }
}

// ============================================================================
// Kernel A: persistent precompute via warp-level bf16 HMMA (unchanged from R6).
// ============================================================================
__global__ __launch_bounds__(128) void prep_kernel(
    const float* __restrict__ x, const float* __restrict__ W1, const float* __restrict__ b1,
    const float* __restrict__ ln_g, const float* __restrict__ ln_b,
    const float* __restrict__ Wi, const float* __restrict__ bi,
    const float* __restrict__ Wc1, const float* __restrict__ bc1)
{
    extern __shared__ __align__(16) char sm[];
    __shared__ float sWi[4][64], sb1[64], slng[64], slnb[64], sbc1[64], sbi[4];

    __nv_bfloat16* hB1 = reinterpret_cast<__nv_bfloat16*>(sm + OFF_B1H);
    __nv_bfloat16* lB1 = reinterpret_cast<__nv_bfloat16*>(sm + OFF_B1L);
    __nv_bfloat16* hB2 = reinterpret_cast<__nv_bfloat16*>(sm + OFF_B2H);
    __nv_bfloat16* lB2 = reinterpret_cast<__nv_bfloat16*>(sm + OFF_B2L);
    const uint32_t* Ah32  = reinterpret_cast<const uint32_t*>(sm + OFF_AH);
    const uint32_t* Al32  = reinterpret_cast<const uint32_t*>(sm + OFF_AL);
    const uint32_t* B1h32 = reinterpret_cast<const uint32_t*>(sm + OFF_B1H);
    const uint32_t* B1l32 = reinterpret_cast<const uint32_t*>(sm + OFF_B1L);
    const uint32_t* B2h32 = reinterpret_cast<const uint32_t*>(sm + OFF_B2H);
    const uint32_t* B2l32 = reinterpret_cast<const uint32_t*>(sm + OFF_B2L);

    const int tid  = threadIdx.x;
    const int lane = tid & 31;
    const int wid  = tid >> 5;
    const int g    = lane >> 2;
    const int t    = lane & 3;
    const int wrow = wid * 16;

#pragma unroll
    for (int it = 0; it < 32; it++) {
        int idx = it * 128 + tid;
        int j = idx >> 6, k = idx & 63;
        float w1v = W1[idx];
        float wcv = Wc1[j * 68 + 4 + k];
        float h1, l1, h2, l2;
        split_bf(w1v, h1, l1);
        split_bf(wcv, h2, l2);
        hB1[j * 72 + k] = __float2bfloat16(h1);
        lB1[j * 72 + k] = __float2bfloat16(l1);
        hB2[j * 72 + k] = __float2bfloat16(h2);
        lB2[j * 72 + k] = __float2bfloat16(l2);
    }
#pragma unroll
    for (int q = tid; q < 256; q += 128) sWi[q >> 6][q & 63] = Wi[q];
    if (tid < 64) {
        sb1[tid]  = b1[tid];
        slng[tid] = ln_g[tid];
        slnb[tid] = ln_b[tid];
        sbc1[tid] = bc1[tid];
        if (tid < 4) sbi[tid] = bi[tid];
    }
    __syncthreads();

    for (int tile = blockIdx.x; tile < NTILE; tile += PREP_GRID) {
        const int tokbase = tile * TILE_T;
        const float4* xg4 = reinterpret_cast<const float4*>(x + (size_t)tokbase * 64);

#pragma unroll
        for (int it = 0; it < 8; it++) {
            int idx = it * 128 + tid;
            float4 v = xg4[idx];
            int row = idx >> 4, c = (idx & 15) * 4;
            float h0, l0, h1, l1, h2, l2, h3, l3;
            split_bf(v.x, h0, l0); split_bf(v.y, h1, l1);
            split_bf(v.z, h2, l2); split_bf(v.w, h3, l3);
            uint32_t* dh = const_cast<uint32_t*>(Ah32) + row * STR32 + (c >> 1);
            uint32_t* dl = const_cast<uint32_t*>(Al32) + row * STR32 + (c >> 1);
            dh[0] = pack_bf2(h0, h1); dh[1] = pack_bf2(h2, h3);
            dl[0] = pack_bf2(l0, l1); dl[1] = pack_bf2(l2, l3);
        }
        __syncthreads();   // B1

        float d[8][4];
#pragma unroll
        for (int nt = 0; nt < 8; nt++)
#pragma unroll
            for (int q = 0; q < 4; q++) d[nt][q] = 0.f;
        gemm_band(d, Ah32, Al32, B1h32, B1l32, wrow, g, t);

        float sA = 0.f, sB = 0.f;
#pragma unroll
        for (int nt = 0; nt < 8; nt++) {
            const int c0 = nt * 8 + 2 * t;
            d[nt][0] += sb1[c0];     d[nt][1] += sb1[c0 + 1];
            d[nt][2] += sb1[c0];     d[nt][3] += sb1[c0 + 1];
            sA += d[nt][0] + d[nt][1];
            sB += d[nt][2] + d[nt][3];
        }
        sA += __shfl_xor_sync(0xffffffffu, sA, 1);
        sA += __shfl_xor_sync(0xffffffffu, sA, 2);
        sB += __shfl_xor_sync(0xffffffffu, sB, 1);
        sB += __shfl_xor_sync(0xffffffffu, sB, 2);
        const float muA = sA * (1.f / 64.f), muB = sB * (1.f / 64.f);
        float qA = 0.f, qB = 0.f;
#pragma unroll
        for (int nt = 0; nt < 8; nt++) {
            float d0 = d[nt][0] - muA, d1 = d[nt][1] - muA;
            float d2 = d[nt][2] - muB, d3 = d[nt][3] - muB;
            qA = fmaf(d0, d0, fmaf(d1, d1, qA));
            qB = fmaf(d2, d2, fmaf(d3, d3, qB));
        }
        qA += __shfl_xor_sync(0xffffffffu, qA, 1);
        qA += __shfl_xor_sync(0xffffffffu, qA, 2);
        qB += __shfl_xor_sync(0xffffffffu, qB, 1);
        qB += __shfl_xor_sync(0xffffffffu, qB, 2);
        const float rsA = rsqrtf(qA * (1.f / 64.f) + 1e-5f);
        const float rsB = rsqrtf(qB * (1.f / 64.f) + 1e-5f);
#pragma unroll
        for (int nt = 0; nt < 8; nt++) {
            const int c0 = nt * 8 + 2 * t;
            const float g0 = slng[c0], g1 = slng[c0 + 1];
            const float o0 = slnb[c0], o1 = slnb[c0 + 1];
            float v0 = fmaf((d[nt][0] - muA) * rsA, g0, o0);
            float v1 = fmaf((d[nt][1] - muA) * rsA, g1, o1);
            float v2 = fmaf((d[nt][2] - muB) * rsB, g0, o0);
            float v3 = fmaf((d[nt][3] - muB) * rsB, g1, o1);
            d[nt][0] = 0.5f * v0 * (1.f + erff(v0 * 0.70710678118654752f));
            d[nt][1] = 0.5f * v1 * (1.f + erff(v1 * 0.70710678118654752f));
            d[nt][2] = 0.5f * v2 * (1.f + erff(v2 * 0.70710678118654752f));
            d[nt][3] = 0.5f * v3 * (1.f + erff(v3 * 0.70710678118654752f));
        }

        {
            float pA[4] = {0.f, 0.f, 0.f, 0.f}, pB[4] = {0.f, 0.f, 0.f, 0.f};
#pragma unroll
            for (int nt = 0; nt < 8; nt++) {
                const int c0 = nt * 8 + 2 * t;
#pragma unroll
                for (int i = 0; i < 4; i++) {
                    const float w0 = sWi[i][c0], w1 = sWi[i][c0 + 1];
                    pA[i] = fmaf(d[nt][0], w0, fmaf(d[nt][1], w1, pA[i]));
                    pB[i] = fmaf(d[nt][2], w0, fmaf(d[nt][3], w1, pB[i]));
                }
            }
#pragma unroll
            for (int i = 0; i < 4; i++) {
                pA[i] += __shfl_xor_sync(0xffffffffu, pA[i], 1);
                pA[i] += __shfl_xor_sync(0xffffffffu, pA[i], 2);
                pB[i] += __shfl_xor_sync(0xffffffffu, pB[i], 1);
                pB[i] += __shfl_xor_sync(0xffffffffu, pB[i], 2);
            }
            if (t == 0) {
                const int rA = tokbase + wrow + g;
                *reinterpret_cast<float4*>(g_bx + (size_t)rA * 4) =
                    make_float4(pA[0] + sbi[0], pA[1] + sbi[1], pA[2] + sbi[2], pA[3] + sbi[3]);
                *reinterpret_cast<float4*>(g_bx + (size_t)(rA + 8) * 4) =
                    make_float4(pB[0] + sbi[0], pB[1] + sbi[1], pB[2] + sbi[2], pB[3] + sbi[3]);
            }
        }
        __syncthreads();   // B2

#pragma unroll
        for (int nt = 0; nt < 8; nt++) {
            const int w0 = (wrow + g) * STR32 + 4 * nt + t;
            const int w1 = (wrow + g + 8) * STR32 + 4 * nt + t;
            float h0, l0, h1, l1, h2, l2, h3, l3;
            split_bf(d[nt][0], h0, l0); split_bf(d[nt][1], h1, l1);
            split_bf(d[nt][2], h2, l2); split_bf(d[nt][3], h3, l3);
            const_cast<uint32_t*>(Ah32)[w0] = pack_bf2(h0, h1);
            const_cast<uint32_t*>(Al32)[w0] = pack_bf2(l0, l1);
            const_cast<uint32_t*>(Ah32)[w1] = pack_bf2(h2, h3);
            const_cast<uint32_t*>(Al32)[w1] = pack_bf2(l2, l3);
        }
        __syncthreads();   // B3

#pragma unroll
        for (int nt = 0; nt < 8; nt++)
#pragma unroll
            for (int q = 0; q < 4; q++) d[nt][q] = 0.f;
        gemm_band(d, Ah32, Al32, B2h32, B2l32, wrow, g, t);

        {
            uint32_t* preA = g_pre_bf + (size_t)(tokbase + wrow + g) * 32;
            uint32_t* preB = preA + 8 * 32;
#pragma unroll
            for (int nt = 0; nt < 8; nt++) {
                const int c0 = nt * 8 + 2 * t;
                const float bc0 = sbc1[c0], bc1v = sbc1[c0 + 1];
                preA[nt * 4 + t] = pack_bf2(d[nt][0] + bc0, d[nt][1] + bc1v);
                preB[nt * 4 + t] = pack_bf2(d[nt][2] + bc0, d[nt][3] + bc1v);
            }
        }
        __syncthreads();   // B4
    }
}

// ============================================================================
// Kernel B: chunked scan, issue-optimized. grid=(BB/2, CHUNKS). Recurrence
// (sl, bx, cs*th add) stays fp32; everything behind the x0.01 correction
// (gelu tanh, second layer, 4-level butterfly, final tanh) runs in half2:
// 2x tanh.approx.f16x2, HFMA2 second layer, packed-half2 butterfly.
// ============================================================================
__global__ __launch_bounds__(32) void scan_kernel(
    const float* __restrict__ Wc1, const float* __restrict__ Wc2, const float* __restrict__ bc2,
    const float* __restrict__ corr_scale,
    const float* __restrict__ A_level, const float* __restrict__ A_trend,
    const float* __restrict__ A_gamma, const float* __restrict__ A_resid,
    const float* __restrict__ omega,
    float* __restrict__ out)
{
    const int lane = threadIdx.x;
    const int half = lane >> 4;
    const int g    = lane & 15;
    const int b    = blockIdx.x * 2 + half;
    const int j0   = g * 4;

    const int outbase = blockIdx.y * CHLEN;
    int start = outbase - WARM;
    if (start < 0) start = 0;
    const int end = outbase + CHLEN;

    float wS[4][4];
    __half2 w2h01[4], w2h23[4];
#pragma unroll
    for (int c = 0; c < 4; c++) {
#pragma unroll
        for (int i = 0; i < 4; i++) wS[c][i] = __ldg(Wc1 + (j0 + c) * 68 + i);
        w2h01[c] = __floats2half2_rn(__ldg(Wc2 + 0 * 64 + j0 + c), __ldg(Wc2 + 1 * 64 + j0 + c));
        w2h23[c] = __floats2half2_rn(__ldg(Wc2 + 2 * 64 + j0 + c), __ldg(Wc2 + 3 * 64 + j0 + c));
    }
    const __half2 bch01 = __floats2half2_rn(__ldg(bc2 + 0) * 0.0625f, __ldg(bc2 + 1) * 0.0625f);
    const __half2 bch23 = __floats2half2_rn(__ldg(bc2 + 2) * 0.0625f, __ldg(bc2 + 3) * 0.0625f);

    const float cs = __ldg(corr_scale);
    const float a0 = sigm(__ldg(A_level)) * 0.15f + 0.85f;
    const float a1 = sigm(__ldg(A_trend)) * 0.25f + 0.7f;
    const float a2 = (sigm(__ldg(A_gamma)) * 0.2f + 0.8f) * cosf(__ldg(omega));
    const float a3 = sigm(__ldg(A_resid)) * 0.4f;
    const float acs0 = a0 * cs, acs1 = a1 * cs, acs2 = a2 * cs, acs3 = a3 * cs;

    const uint2* prw = reinterpret_cast<const uint2*>(g_pre_bf + (size_t)b * SS * 32) + g;
    const float* bxp = g_bx + ((size_t)b * SS) * 4;
    float* outp      = out  + ((size_t)b * SS) * 4;

    float v0 = 0.f, v1 = 0.f, v2 = 0.f, v3 = 0.f;
    float th0 = 0.f, th1 = 0.f, th2 = 0.f, th3 = 0.f;

    uint2 prb[8];
    float4 bxb[8];
#pragma unroll
    for (int i = 0; i < 8; i++) {
        prb[i] = __ldcs(prw + (size_t)(start + i) * 16);
        bxb[i] = __ldg(reinterpret_cast<const float4*>(bxp + (size_t)(start + i) * 4));
    }

    for (int tb = start; tb < end; tb += 8) {
#pragma unroll
        for (int u = 0; u < 8; u++) {
            const int t = tb + u;
            uint2 pru = prb[u];
            float4 bx = bxb[u];

            int tp = t + 8;
            if (tp > SS - 1) tp = SS - 1;
            prb[u] = __ldcs(prw + (size_t)tp * 16);
            bxb[u] = __ldg(reinterpret_cast<const float4*>(bxp + (size_t)tp * 4));

            float2 f01 = __bfloat1622float2(*reinterpret_cast<__nv_bfloat162*>(&pru.x));
            float2 f23 = __bfloat1622float2(*reinterpret_cast<__nv_bfloat162*>(&pru.y));

            // fp32 recurrence (main path)
            float sl0 = fmaf(acs0, th0, fmaf(a0, v0, bx.x));
            float sl1 = fmaf(acs1, th1, fmaf(a1, v1, bx.y));
            float sl2 = fmaf(acs2, th2, fmaf(a2, v2, bx.z));
            float sl3 = fmaf(acs3, th3, fmaf(a3, v3, bx.w));

            float uu0 = fmaf(sl1, wS[0][1], fmaf(sl0, wS[0][0], f01.x)) + fmaf(sl3, wS[0][3], sl2 * wS[0][2]);
            float uu1 = fmaf(sl1, wS[1][1], fmaf(sl0, wS[1][0], f01.y)) + fmaf(sl3, wS[1][3], sl2 * wS[1][2]);
            float uu2 = fmaf(sl1, wS[2][1], fmaf(sl0, wS[2][0], f23.x)) + fmaf(sl3, wS[2][3], sl2 * wS[2][2]);
            float uu3 = fmaf(sl1, wS[3][1], fmaf(sl0, wS[3][0], f23.y)) + fmaf(sl3, wS[3][3], sl2 * wS[3][2]);

            // gelu argument in f32, tanh in f16x2 (damped x0.01 downstream)
            float in0 = uu0 * fmaf(0.0356774081f, uu0 * uu0, 0.7978845608f);
            float in1 = uu1 * fmaf(0.0356774081f, uu1 * uu1, 0.7978845608f);
            float in2 = uu2 * fmaf(0.0356774081f, uu2 * uu2, 0.7978845608f);
            float in3 = uu3 * fmaf(0.0356774081f, uu3 * uu3, 0.7978845608f);
            __half2 t01 = tanh2(__floats2half2_rn(in0, in1));
            __half2 t23 = tanh2(__floats2half2_rn(in2, in3));
            __half2 uh01 = __floats2half2_rn(0.5f * uu0, 0.5f * uu1);
            __half2 uh23 = __floats2half2_rn(0.5f * uu2, 0.5f * uu3);
            __half2 g01 = __hfma2(t01, uh01, uh01);
            __half2 g23 = __hfma2(t23, uh23, uh23);

            // second layer in HFMA2: p01=(p0,p1), p23=(p2,p3)
            __half2 d0 = __low2half2(g01), d1 = __high2half2(g01);
            __half2 d2 = __low2half2(g23), d3 = __high2half2(g23);
            __half2 p01 = __hfma2(d0, w2h01[0], bch01);
            p01 = __hfma2(d1, w2h01[1], p01);
            p01 = __hfma2(d2, w2h01[2], p01);
            p01 = __hfma2(d3, w2h01[3], p01);
            __half2 p23 = __hfma2(d0, w2h23[0], bch23);
            p23 = __hfma2(d1, w2h23[1], p23);
            p23 = __hfma2(d2, w2h23[2], p23);
            p23 = __hfma2(d3, w2h23[3], p23);

            // 4-level packed butterfly within each 16-lane group
#pragma unroll
            for (int off = 8; off; off >>= 1) {
                p01 = __hadd2(p01, shfl_xor_h2(p01, off));
                p23 = __hadd2(p23, shfl_xor_h2(p23, off));
            }
            __half2 q01 = tanh2(p01);
            __half2 q23 = tanh2(p23);
            float nth0 = __low2float(q01), nth1 = __high2float(q01);
            float nth2 = __low2float(q23), nth3 = __high2float(q23);

            if ((g == 0) && (t >= outbase)) {
                float4 so = make_float4(fmaf(cs, nth0, sl0), fmaf(cs, nth1, sl1),
                                        fmaf(cs, nth2, sl2), fmaf(cs, nth3, sl3));
                *reinterpret_cast<float4*>(outp + (size_t)t * 4) = so;
            }

            v0 = sl0; v1 = sl1; v2 = sl2; v3 = sl3;
            th0 = nth0; th1 = nth1; th2 = nth2; th3 = nth3;
        }
    }
}

extern "C" void kernel_launch(void* const* d_in, const int* in_sizes, int n_in,
                              void* d_out, int out_size)
{
    const float* x          = (const float*)d_in[0];
    const float* W1         = (const float*)d_in[1];
    const float* b1         = (const float*)d_in[2];
    const float* ln_g       = (const float*)d_in[3];
    const float* ln_b       = (const float*)d_in[4];
    const float* Wi         = (const float*)d_in[5];
    const float* bi         = (const float*)d_in[6];
    const float* Wc1        = (const float*)d_in[7];
    const float* bc1        = (const float*)d_in[8];
    const float* Wc2        = (const float*)d_in[9];
    const float* bc2        = (const float*)d_in[10];
    const float* corr_scale = (const float*)d_in[11];
    const float* A_level    = (const float*)d_in[12];
    const float* A_trend    = (const float*)d_in[13];
    const float* A_gamma    = (const float*)d_in[14];
    const float* A_resid    = (const float*)d_in[15];
    const float* omega      = (const float*)d_in[16];
    float* out = (float*)d_out;

    cudaFuncSetAttribute(prep_kernel, cudaFuncAttributeMaxDynamicSharedMemorySize, SMEM_DYN);
    prep_kernel<<<PREP_GRID, 128, SMEM_DYN>>>(x, W1, b1, ln_g, ln_b, Wi, bi, Wc1, bc1);
    dim3 sgrid(BB / 2, CHUNKS);
    scan_kernel<<<sgrid, 32>>>(Wc1, Wc2, bc2, corr_scale,
                               A_level, A_trend, A_gamma, A_resid, omega, out);
}

// round 8
// speedup vs baseline: 4.0054x; 1.0308x over previous
#include <cuda_runtime.h>
#include <cuda_bf16.h>
#include <cuda_fp16.h>
#include <math.h>
#include <stdint.h>

#define BB 512
#define SS 1024
#define TILE_T 64
#define NTILE ((BB * SS) / TILE_T)   // 8192 tiles of 64 tokens
#define PREP_GRID 444                // 148 SMs * 3 blocks (55KB smem each)

#define CHUNKS 8
#define CHLEN (SS / CHUNKS)          // 128
#define WARM 160                     // 0.925^160 ~ 3.8e-6 forgetting

// bf16 smem tiles: 64 rows x 72 bf16 (144B stride = 36 u32) -> conflict-free frags
#define STR32 36
#define TBYTES (64 * 72 * 2)         // 9216
#define OFF_AH  0
#define OFF_AL  (TBYTES)
#define OFF_B1H (2 * TBYTES)
#define OFF_B1L (3 * TBYTES)
#define OFF_B2H (4 * TBYTES)
#define OFF_B2L (5 * TBYTES)
#define SMEM_DYN (6 * TBYTES)        // 55296 bytes

// Scratch (static device globals — allocation-guard-safe)
__device__ uint32_t g_pre_h[BB * SS * 32];   // 67 MB: f16x2-packed pre
__device__ float g_bx[BB * SS * 4];          // 8 MB

__device__ __forceinline__ float sigm(float x) { return 1.f / (1.f + expf(-x)); }

__device__ __forceinline__ uint32_t pack_bf2(float a, float b) {
    __nv_bfloat162 v = __halves2bfloat162(__float2bfloat16(a), __float2bfloat16(b));
    return *reinterpret_cast<uint32_t*>(&v);
}
__device__ __forceinline__ uint32_t pack_h2(float a, float b) {
    __half2 v = __floats2half2_rn(a, b);
    return *reinterpret_cast<uint32_t*>(&v);
}
__device__ __forceinline__ void split_bf(float v, float& hi, float& lo) {
    hi = __bfloat162float(__float2bfloat16(v));
    lo = v - hi;
}
__device__ __forceinline__ __half2 tanh2(__half2 x) {
    __half2 y;
    asm("tanh.approx.f16x2 %0, %1;"
        : "=r"(*reinterpret_cast<uint32_t*>(&y))
        : "r"(*reinterpret_cast<uint32_t*>(&x)));
    return y;
}
__device__ __forceinline__ __half2 shfl_xor_h2(__half2 v, int off) {
    uint32_t u = *reinterpret_cast<uint32_t*>(&v);
    u = __shfl_xor_sync(0xffffffffu, u, off);
    return *reinterpret_cast<__half2*>(&u);
}

// mma.sync m16n8k16 bf16 (base ISA, compiles under compute_103)
__device__ __forceinline__ void mma16816(float d[4], uint32_t a0, uint32_t a1,
                                         uint32_t a2, uint32_t a3,
                                         uint32_t b0, uint32_t b1) {
    asm volatile(
        "mma.sync.aligned.m16n8k16.row.col.f32.bf16.bf16.f32 "
        "{%0,%1,%2,%3}, {%4,%5,%6,%7}, {%8,%9}, {%0,%1,%2,%3};"
        : "+f"(d[0]), "+f"(d[1]), "+f"(d[2]), "+f"(d[3])
        : "r"(a0), "r"(a1), "r"(a2), "r"(a3), "r"(b0), "r"(b1));
}

// One 16x64 output tile: D += A(16x64) @ B^T(64x64), 3-product split precision.
__device__ __forceinline__ void gemm_band(
    float d[8][4], const uint32_t* __restrict__ Ah, const uint32_t* __restrict__ Al,
    const uint32_t* __restrict__ Bh, const uint32_t* __restrict__ Bl,
    int warp_row, int g, int t)
{
#pragma unroll
    for (int ks = 0; ks < 4; ks++) {
        const int aw = (warp_row + g) * STR32 + 8 * ks + t;
        const uint32_t ah0 = Ah[aw],               ah1 = Ah[aw + 8 * STR32];
        const uint32_t ah2 = Ah[aw + 4],           ah3 = Ah[aw + 8 * STR32 + 4];
        const uint32_t al0 = Al[aw],               al1 = Al[aw + 8 * STR32];
        const uint32_t al2 = Al[aw + 4],           al3 = Al[aw + 8 * STR32 + 4];
#pragma unroll
        for (int nt = 0; nt < 8; nt++) {
            const int bw = (nt * 8 + g) * STR32 + 8 * ks + t;
            const uint32_t bh0 = Bh[bw], bh1 = Bh[bw + 4];
            const uint32_t bl0 = Bl[bw], bl1 = Bl[bw + 4];
            mma16816(d[nt], ah0, ah1, ah2, ah3, bh0, bh1);
            mma16816(d[nt], al0, al1, al2, al3, bh0, bh1);
            mma16816(d[nt], ah0, ah1, ah2, ah3, bl0, bl1);
        }
    }
}

// ============================================================================
// Kernel A: persistent precompute via warp-level bf16 HMMA (R6 structure;
// only change: pre stored as f16x2 instead of bf16x2).
// ============================================================================
__global__ __launch_bounds__(128) void prep_kernel(
    const float* __restrict__ x, const float* __restrict__ W1, const float* __restrict__ b1,
    const float* __restrict__ ln_g, const float* __restrict__ ln_b,
    const float* __restrict__ Wi, const float* __restrict__ bi,
    const float* __restrict__ Wc1, const float* __restrict__ bc1)
{
    extern __shared__ __align__(16) char sm[];
    __shared__ float sWi[4][64], sb1[64], slng[64], slnb[64], sbc1[64], sbi[4];

    __nv_bfloat16* hB1 = reinterpret_cast<__nv_bfloat16*>(sm + OFF_B1H);
    __nv_bfloat16* lB1 = reinterpret_cast<__nv_bfloat16*>(sm + OFF_B1L);
    __nv_bfloat16* hB2 = reinterpret_cast<__nv_bfloat16*>(sm + OFF_B2H);
    __nv_bfloat16* lB2 = reinterpret_cast<__nv_bfloat16*>(sm + OFF_B2L);
    const uint32_t* Ah32  = reinterpret_cast<const uint32_t*>(sm + OFF_AH);
    const uint32_t* Al32  = reinterpret_cast<const uint32_t*>(sm + OFF_AL);
    const uint32_t* B1h32 = reinterpret_cast<const uint32_t*>(sm + OFF_B1H);
    const uint32_t* B1l32 = reinterpret_cast<const uint32_t*>(sm + OFF_B1L);
    const uint32_t* B2h32 = reinterpret_cast<const uint32_t*>(sm + OFF_B2H);
    const uint32_t* B2l32 = reinterpret_cast<const uint32_t*>(sm + OFF_B2L);

    const int tid  = threadIdx.x;
    const int lane = tid & 31;
    const int wid  = tid >> 5;
    const int g    = lane >> 2;
    const int t    = lane & 3;
    const int wrow = wid * 16;

#pragma unroll
    for (int it = 0; it < 32; it++) {
        int idx = it * 128 + tid;
        int j = idx >> 6, k = idx & 63;
        float w1v = W1[idx];
        float wcv = Wc1[j * 68 + 4 + k];
        float h1, l1, h2, l2;
        split_bf(w1v, h1, l1);
        split_bf(wcv, h2, l2);
        hB1[j * 72 + k] = __float2bfloat16(h1);
        lB1[j * 72 + k] = __float2bfloat16(l1);
        hB2[j * 72 + k] = __float2bfloat16(h2);
        lB2[j * 72 + k] = __float2bfloat16(l2);
    }
#pragma unroll
    for (int q = tid; q < 256; q += 128) sWi[q >> 6][q & 63] = Wi[q];
    if (tid < 64) {
        sb1[tid]  = b1[tid];
        slng[tid] = ln_g[tid];
        slnb[tid] = ln_b[tid];
        sbc1[tid] = bc1[tid];
        if (tid < 4) sbi[tid] = bi[tid];
    }
    __syncthreads();

    for (int tile = blockIdx.x; tile < NTILE; tile += PREP_GRID) {
        const int tokbase = tile * TILE_T;
        const float4* xg4 = reinterpret_cast<const float4*>(x + (size_t)tokbase * 64);

#pragma unroll
        for (int it = 0; it < 8; it++) {
            int idx = it * 128 + tid;
            float4 v = xg4[idx];
            int row = idx >> 4, c = (idx & 15) * 4;
            float h0, l0, h1, l1, h2, l2, h3, l3;
            split_bf(v.x, h0, l0); split_bf(v.y, h1, l1);
            split_bf(v.z, h2, l2); split_bf(v.w, h3, l3);
            uint32_t* dh = const_cast<uint32_t*>(Ah32) + row * STR32 + (c >> 1);
            uint32_t* dl = const_cast<uint32_t*>(Al32) + row * STR32 + (c >> 1);
            dh[0] = pack_bf2(h0, h1); dh[1] = pack_bf2(h2, h3);
            dl[0] = pack_bf2(l0, l1); dl[1] = pack_bf2(l2, l3);
        }
        __syncthreads();   // B1

        float d[8][4];
#pragma unroll
        for (int nt = 0; nt < 8; nt++)
#pragma unroll
            for (int q = 0; q < 4; q++) d[nt][q] = 0.f;
        gemm_band(d, Ah32, Al32, B1h32, B1l32, wrow, g, t);

        float sA = 0.f, sB = 0.f;
#pragma unroll
        for (int nt = 0; nt < 8; nt++) {
            const int c0 = nt * 8 + 2 * t;
            d[nt][0] += sb1[c0];     d[nt][1] += sb1[c0 + 1];
            d[nt][2] += sb1[c0];     d[nt][3] += sb1[c0 + 1];
            sA += d[nt][0] + d[nt][1];
            sB += d[nt][2] + d[nt][3];
        }
        sA += __shfl_xor_sync(0xffffffffu, sA, 1);
        sA += __shfl_xor_sync(0xffffffffu, sA, 2);
        sB += __shfl_xor_sync(0xffffffffu, sB, 1);
        sB += __shfl_xor_sync(0xffffffffu, sB, 2);
        const float muA = sA * (1.f / 64.f), muB = sB * (1.f / 64.f);
        float qA = 0.f, qB = 0.f;
#pragma unroll
        for (int nt = 0; nt < 8; nt++) {
            float d0 = d[nt][0] - muA, d1 = d[nt][1] - muA;
            float d2 = d[nt][2] - muB, d3 = d[nt][3] - muB;
            qA = fmaf(d0, d0, fmaf(d1, d1, qA));
            qB = fmaf(d2, d2, fmaf(d3, d3, qB));
        }
        qA += __shfl_xor_sync(0xffffffffu, qA, 1);
        qA += __shfl_xor_sync(0xffffffffu, qA, 2);
        qB += __shfl_xor_sync(0xffffffffu, qB, 1);
        qB += __shfl_xor_sync(0xffffffffu, qB, 2);
        const float rsA = rsqrtf(qA * (1.f / 64.f) + 1e-5f);
        const float rsB = rsqrtf(qB * (1.f / 64.f) + 1e-5f);
#pragma unroll
        for (int nt = 0; nt < 8; nt++) {
            const int c0 = nt * 8 + 2 * t;
            const float g0 = slng[c0], g1 = slng[c0 + 1];
            const float o0 = slnb[c0], o1 = slnb[c0 + 1];
            float v0 = fmaf((d[nt][0] - muA) * rsA, g0, o0);
            float v1 = fmaf((d[nt][1] - muA) * rsA, g1, o1);
            float v2 = fmaf((d[nt][2] - muB) * rsB, g0, o0);
            float v3 = fmaf((d[nt][3] - muB) * rsB, g1, o1);
            d[nt][0] = 0.5f * v0 * (1.f + erff(v0 * 0.70710678118654752f));
            d[nt][1] = 0.5f * v1 * (1.f + erff(v1 * 0.70710678118654752f));
            d[nt][2] = 0.5f * v2 * (1.f + erff(v2 * 0.70710678118654752f));
            d[nt][3] = 0.5f * v3 * (1.f + erff(v3 * 0.70710678118654752f));
        }

        {
            float pA[4] = {0.f, 0.f, 0.f, 0.f}, pB[4] = {0.f, 0.f, 0.f, 0.f};
#pragma unroll
            for (int nt = 0; nt < 8; nt++) {
                const int c0 = nt * 8 + 2 * t;
#pragma unroll
                for (int i = 0; i < 4; i++) {
                    const float w0 = sWi[i][c0], w1 = sWi[i][c0 + 1];
                    pA[i] = fmaf(d[nt][0], w0, fmaf(d[nt][1], w1, pA[i]));
                    pB[i] = fmaf(d[nt][2], w0, fmaf(d[nt][3], w1, pB[i]));
                }
            }
#pragma unroll
            for (int i = 0; i < 4; i++) {
                pA[i] += __shfl_xor_sync(0xffffffffu, pA[i], 1);
                pA[i] += __shfl_xor_sync(0xffffffffu, pA[i], 2);
                pB[i] += __shfl_xor_sync(0xffffffffu, pB[i], 1);
                pB[i] += __shfl_xor_sync(0xffffffffu, pB[i], 2);
            }
            if (t == 0) {
                const int rA = tokbase + wrow + g;
                *reinterpret_cast<float4*>(g_bx + (size_t)rA * 4) =
                    make_float4(pA[0] + sbi[0], pA[1] + sbi[1], pA[2] + sbi[2], pA[3] + sbi[3]);
                *reinterpret_cast<float4*>(g_bx + (size_t)(rA + 8) * 4) =
                    make_float4(pB[0] + sbi[0], pB[1] + sbi[1], pB[2] + sbi[2], pB[3] + sbi[3]);
            }
        }
        __syncthreads();   // B2

#pragma unroll
        for (int nt = 0; nt < 8; nt++) {
            const int w0 = (wrow + g) * STR32 + 4 * nt + t;
            const int w1 = (wrow + g + 8) * STR32 + 4 * nt + t;
            float h0, l0, h1, l1, h2, l2, h3, l3;
            split_bf(d[nt][0], h0, l0); split_bf(d[nt][1], h1, l1);
            split_bf(d[nt][2], h2, l2); split_bf(d[nt][3], h3, l3);
            const_cast<uint32_t*>(Ah32)[w0] = pack_bf2(h0, h1);
            const_cast<uint32_t*>(Al32)[w0] = pack_bf2(l0, l1);
            const_cast<uint32_t*>(Ah32)[w1] = pack_bf2(h2, h3);
            const_cast<uint32_t*>(Al32)[w1] = pack_bf2(l2, l3);
        }
        __syncthreads();   // B3

#pragma unroll
        for (int nt = 0; nt < 8; nt++)
#pragma unroll
            for (int q = 0; q < 4; q++) d[nt][q] = 0.f;
        gemm_band(d, Ah32, Al32, B2h32, B2l32, wrow, g, t);

        {
            uint32_t* preA = g_pre_h + (size_t)(tokbase + wrow + g) * 32;
            uint32_t* preB = preA + 8 * 32;
#pragma unroll
            for (int nt = 0; nt < 8; nt++) {
                const int c0 = nt * 8 + 2 * t;
                const float bc0 = sbc1[c0], bc1v = sbc1[c0 + 1];
                preA[nt * 4 + t] = pack_h2(d[nt][0] + bc0, d[nt][1] + bc1v);
                preB[nt * 4 + t] = pack_h2(d[nt][2] + bc0, d[nt][3] + bc1v);
            }
        }
        __syncthreads();   // B4
    }
}

// ============================================================================
// Kernel B: chunked scan. grid=(BB/4, CHUNKS); 8 lanes/batch, 4 batches/warp,
// 8 MLP cols/lane. fp32 recurrence; uu+gelu+layer2+3-level butterfly in half2;
// pre loads are native f16x2. bc2 folded as bc2/8.
// ============================================================================
__global__ __launch_bounds__(32) void scan_kernel(
    const float* __restrict__ Wc1, const float* __restrict__ Wc2, const float* __restrict__ bc2,
    const float* __restrict__ corr_scale,
    const float* __restrict__ A_level, const float* __restrict__ A_trend,
    const float* __restrict__ A_gamma, const float* __restrict__ A_resid,
    const float* __restrict__ omega,
    float* __restrict__ out)
{
    const int lane = threadIdx.x;
    const int grp  = lane >> 3;     // batch within warp
    const int g8   = lane & 7;      // lane within batch group
    const int b    = blockIdx.x * 4 + grp;
    const int j0   = g8 * 8;

    const int outbase = blockIdx.y * CHLEN;
    int start = outbase - WARM;
    if (start < 0) start = 0;
    const int end = outbase + CHLEN;

    // wS2[i][pp] = (Wc1[j0+2pp][i], Wc1[j0+2pp+1][i])
    __half2 wS2[4][4];
#pragma unroll
    for (int pp = 0; pp < 4; pp++)
#pragma unroll
        for (int i = 0; i < 4; i++)
            wS2[i][pp] = __floats2half2_rn(__ldg(Wc1 + (j0 + 2 * pp) * 68 + i),
                                           __ldg(Wc1 + (j0 + 2 * pp + 1) * 68 + i));
    __half2 w2a[8], w2b[8];
#pragma unroll
    for (int k = 0; k < 8; k++) {
        w2a[k] = __floats2half2_rn(__ldg(Wc2 + 0 * 64 + j0 + k), __ldg(Wc2 + 1 * 64 + j0 + k));
        w2b[k] = __floats2half2_rn(__ldg(Wc2 + 2 * 64 + j0 + k), __ldg(Wc2 + 3 * 64 + j0 + k));
    }
    const __half2 bca = __floats2half2_rn(__ldg(bc2 + 0) * 0.125f, __ldg(bc2 + 1) * 0.125f);
    const __half2 bcb = __floats2half2_rn(__ldg(bc2 + 2) * 0.125f, __ldg(bc2 + 3) * 0.125f);
    const __half2 C1h = __float2half2_rn(0.7978845608f);
    const __half2 C2h = __float2half2_rn(0.0356774081f);
    const __half2 Hh  = __float2half2_rn(0.5f);

    const float cs = __ldg(corr_scale);
    const float a0 = sigm(__ldg(A_level)) * 0.15f + 0.85f;
    const float a1 = sigm(__ldg(A_trend)) * 0.25f + 0.7f;
    const float a2 = (sigm(__ldg(A_gamma)) * 0.2f + 0.8f) * cosf(__ldg(omega));
    const float a3 = sigm(__ldg(A_resid)) * 0.4f;
    const float acs0 = a0 * cs, acs1 = a1 * cs, acs2 = a2 * cs, acs3 = a3 * cs;

    // f16 pre: 8 uint4 per token; lane g8 reads uint4 #g8 (its 8 cols)
    const uint4* prw = reinterpret_cast<const uint4*>(g_pre_h + (size_t)b * SS * 32) + g8;
    const float* bxp = g_bx + ((size_t)b * SS) * 4;
    float* outp      = out  + ((size_t)b * SS) * 4;

    float v0 = 0.f, v1 = 0.f, v2 = 0.f, v3 = 0.f;
    float th0 = 0.f, th1 = 0.f, th2 = 0.f, th3 = 0.f;

    uint4 prb[8];
    float4 bxb[8];
#pragma unroll
    for (int i = 0; i < 8; i++) {
        prb[i] = __ldcs(prw + (size_t)(start + i) * 8);
        bxb[i] = __ldg(reinterpret_cast<const float4*>(bxp + (size_t)(start + i) * 4));
    }

    for (int tb = start; tb < end; tb += 8) {
#pragma unroll
        for (int u = 0; u < 8; u++) {
            const int t = tb + u;
            uint4 pru = prb[u];
            float4 bx = bxb[u];

            int tp = t + 8;
            if (tp > SS - 1) tp = SS - 1;
            prb[u] = __ldcs(prw + (size_t)tp * 8);
            bxb[u] = __ldg(reinterpret_cast<const float4*>(bxp + (size_t)tp * 4));

            // fp32 recurrence
            float sl0 = fmaf(acs0, th0, fmaf(a0, v0, bx.x));
            float sl1 = fmaf(acs1, th1, fmaf(a1, v1, bx.y));
            float sl2 = fmaf(acs2, th2, fmaf(a2, v2, bx.z));
            float sl3 = fmaf(acs3, th3, fmaf(a3, v3, bx.w));

            // broadcast to half2
            __half2 sb0 = __float2half2_rn(sl0);
            __half2 sb1 = __float2half2_rn(sl1);
            __half2 sb2 = __float2half2_rn(sl2);
            __half2 sb3 = __float2half2_rn(sl3);

            // uu[pp] = pre_pp + sl @ Wc1s (half2)
            __half2 uu[4];
            const __half2* pp2 = reinterpret_cast<const __half2*>(&pru);
#pragma unroll
            for (int pp = 0; pp < 4; pp++) {
                __half2 acc = __hfma2(sb0, wS2[0][pp], pp2[pp]);
                acc = __hfma2(sb1, wS2[1][pp], acc);
                acc = __hfma2(sb2, wS2[2][pp], acc);
                uu[pp] = __hfma2(sb3, wS2[3][pp], acc);
            }

            // fast GELU in half2
            __half2 gp[4];
#pragma unroll
            for (int pp = 0; pp < 4; pp++) {
                __half2 q  = __hmul2(uu[pp], uu[pp]);
                __half2 in = __hmul2(uu[pp], __hfma2(C2h, q, C1h));
                __half2 tt = tanh2(in);
                __half2 uh = __hmul2(Hh, uu[pp]);
                gp[pp] = __hfma2(tt, uh, uh);
            }

            // second layer (two-accumulator trees), bc2/8 folded
            __half2 pa0 = __hfma2(__low2half2(gp[0]), w2a[0], bca);
            __half2 pa1 = __hfma2(__high2half2(gp[0]), w2a[1], __hmul2(__low2half2(gp[1]), w2a[2]));
            pa0 = __hfma2(__high2half2(gp[1]), w2a[3], pa0);
            pa1 = __hfma2(__low2half2(gp[2]),  w2a[4], pa1);
            pa0 = __hfma2(__high2half2(gp[2]), w2a[5], pa0);
            pa1 = __hfma2(__low2half2(gp[3]),  w2a[6], pa1);
            pa0 = __hfma2(__high2half2(gp[3]), w2a[7], pa0);
            __half2 p01 = __hadd2(pa0, pa1);

            __half2 pb0 = __hfma2(__low2half2(gp[0]), w2b[0], bcb);
            __half2 pb1 = __hfma2(__high2half2(gp[0]), w2b[1], __hmul2(__low2half2(gp[1]), w2b[2]));
            pb0 = __hfma2(__high2half2(gp[1]), w2b[3], pb0);
            pb1 = __hfma2(__low2half2(gp[2]),  w2b[4], pb1);
            pb0 = __hfma2(__high2half2(gp[2]), w2b[5], pb0);
            pb1 = __hfma2(__low2half2(gp[3]),  w2b[6], pb1);
            pb0 = __hfma2(__high2half2(gp[3]), w2b[7], pb0);
            __half2 p23 = __hadd2(pb0, pb1);

            // 3-level packed butterfly within each 8-lane group
#pragma unroll
            for (int off = 4; off; off >>= 1) {
                p01 = __hadd2(p01, shfl_xor_h2(p01, off));
                p23 = __hadd2(p23, shfl_xor_h2(p23, off));
            }
            __half2 q01 = tanh2(p01);
            __half2 q23 = tanh2(p23);
            float nth0 = __low2float(q01), nth1 = __high2float(q01);
            float nth2 = __low2float(q23), nth3 = __high2float(q23);

            if ((g8 == 0) && (t >= outbase)) {
                float4 so = make_float4(fmaf(cs, nth0, sl0), fmaf(cs, nth1, sl1),
                                        fmaf(cs, nth2, sl2), fmaf(cs, nth3, sl3));
                *reinterpret_cast<float4*>(outp + (size_t)t * 4) = so;
            }

            v0 = sl0; v1 = sl1; v2 = sl2; v3 = sl3;
            th0 = nth0; th1 = nth1; th2 = nth2; th3 = nth3;
        }
    }
}

extern "C" void kernel_launch(void* const* d_in, const int* in_sizes, int n_in,
                              void* d_out, int out_size)
{
    const float* x          = (const float*)d_in[0];
    const float* W1         = (const float*)d_in[1];
    const float* b1         = (const float*)d_in[2];
    const float* ln_g       = (const float*)d_in[3];
    const float* ln_b       = (const float*)d_in[4];
    const float* Wi         = (const float*)d_in[5];
    const float* bi         = (const float*)d_in[6];
    const float* Wc1        = (const float*)d_in[7];
    const float* bc1        = (const float*)d_in[8];
    const float* Wc2        = (const float*)d_in[9];
    const float* bc2        = (const float*)d_in[10];
    const float* corr_scale = (const float*)d_in[11];
    const float* A_level    = (const float*)d_in[12];
    const float* A_trend    = (const float*)d_in[13];
    const float* A_gamma    = (const float*)d_in[14];
    const float* A_resid    = (const float*)d_in[15];
    const float* omega      = (const float*)d_in[16];
    float* out = (float*)d_out;

    cudaFuncSetAttribute(prep_kernel, cudaFuncAttributeMaxDynamicSharedMemorySize, SMEM_DYN);
    prep_kernel<<<PREP_GRID, 128, SMEM_DYN>>>(x, W1, b1, ln_g, ln_b, Wi, bi, Wc1, bc1);
    dim3 sgrid(BB / 4, CHUNKS);
    scan_kernel<<<sgrid, 32>>>(Wc1, Wc2, bc2, corr_scale,
                               A_level, A_trend, A_gamma, A_resid, omega, out);
}